// round 8
// baseline (speedup 1.0000x reference)
#include <cuda_runtime.h>
#include <cuda_bf16.h>
#include <cstdint>

#define N_NODES   100000
#define MAX_EDGES 3400000
#define IN_DIM    512
#define HIDDEN    256
#define N_CLASSES 1000

// ---------------------------------------------------------------------------
// Scratch: __device__ globals (allocation-free per harness rules)
// ---------------------------------------------------------------------------
__device__ int   g_is64;                 // 1 if edge_index is int64, 0 if int32
__device__ int   g_cnt[N_NODES];
__device__ int   g_cursor[N_NODES];
__device__ int   g_rowptr[N_NODES + 1];
__device__ float g_dinv[N_NODES];
__device__ int   g_csr_src[MAX_EDGES];
__device__ float g_csr_nrm[MAX_EDGES];
__device__ __align__(16) float g_h[(size_t)N_NODES * HIDDEN];    // GEMM out
__device__ __align__(16) float g_agg[(size_t)N_NODES * HIDDEN];  // gather out

// fetch edge endpoint i (0-based into a logical int array of length 2E)
__device__ __forceinline__ int edge_at(const void* ei, long long i) {
    if (g_is64) {
        long long v = ((const long long*)ei)[i];
        return (int)v;
    }
    return ((const int*)ei)[i];
}

__device__ __forceinline__ int clamp_node(int v) {
    return (v < 0) ? 0 : (v >= N_NODES ? N_NODES - 1 : v);
}

// ---------------------------------------------------------------------------
// dtype detect: int64 node ids < 2^31 have all-zero odd 32-bit words
// ---------------------------------------------------------------------------
__global__ void gnn3_detect_kernel(const int* __restrict__ ei32) {
    if (threadIdx.x == 0 && blockIdx.x == 0) {
        int nonzero = 0;
        for (int i = 0; i < 2048; i++)
            if (ei32[2 * i + 1] != 0) nonzero++;
        g_is64 = (nonzero == 0) ? 1 : 0;
    }
}

// ---------------------------------------------------------------------------
// CSR build
// ---------------------------------------------------------------------------
__global__ void gnn3_init_kernel() {
    int i = blockIdx.x * blockDim.x + threadIdx.x;
    if (i < N_NODES) { g_cnt[i] = 0; g_cursor[i] = 0; }
}

__global__ void gnn3_count_kernel(const void* __restrict__ ei, int E) {
    int e = blockIdx.x * blockDim.x + threadIdx.x;
    if (e < E) {
        int c = clamp_node(edge_at(ei, (long long)E + e));   // target
        atomicAdd(&g_cnt[c], 1);
    }
}

// single-block exclusive scan of g_cnt -> g_rowptr (1024 threads)
__global__ void gnn3_scan_kernel() {
    __shared__ int ssum[1024];
    const int t = threadIdx.x;
    const int CHUNK = (N_NODES + 1023) / 1024;     // 98
    int beg = t * CHUNK;
    int end = min(beg + CHUNK, N_NODES);
    int s = 0;
    for (int i = beg; i < end; i++) s += g_cnt[i];
    ssum[t] = s;
    __syncthreads();
    for (int off = 1; off < 1024; off <<= 1) {
        int v = 0;
        if (t >= off) v = ssum[t - off];
        __syncthreads();
        if (t >= off) ssum[t] += v;
        __syncthreads();
    }
    int run = (t == 0) ? 0 : ssum[t - 1];
    for (int i = beg; i < end; i++) {
        g_rowptr[i] = run;
        run += g_cnt[i];
    }
    if (t == 0) g_rowptr[N_NODES] = ssum[1023];
}

__global__ void gnn3_dinv_kernel() {
    int i = blockIdx.x * blockDim.x + threadIdx.x;
    if (i < N_NODES) g_dinv[i] = rsqrtf((float)g_cnt[i] + 1.0f); // +1 self loop
}

__global__ void gnn3_fill_kernel(const void* __restrict__ ei, int E) {
    int e = blockIdx.x * blockDim.x + threadIdx.x;
    if (e >= E) return;
    int r = clamp_node(edge_at(ei, e));                    // source
    int c = clamp_node(edge_at(ei, (long long)E + e));     // target
    int pos = atomicAdd(&g_cursor[c], 1);
    int idx = g_rowptr[c] + pos;
    if (idx >= 0 && idx < MAX_EDGES) {
        g_csr_src[idx] = r;
        g_csr_nrm[idx] = g_dinv[r] * g_dinv[c];
    }
}

// ---------------------------------------------------------------------------
// pull-gather: one warp per target node. Reads g_h, writes g_agg.
// g_agg[n] = relu( sum_e g_h[src_e]*nrm_e + g_h[n]*dinv[n]^2 + bias )
// ---------------------------------------------------------------------------
__global__ __launch_bounds__(256)
void gnn3_gather_kernel(const float* __restrict__ bias) {
    int warp = (blockIdx.x * blockDim.x + threadIdx.x) >> 5;
    int lane = threadIdx.x & 31;
    if (warp >= N_NODES) return;
    const int node = warp;

    float s  = g_dinv[node];
    float s2 = s * s;

    const float4* hn = (const float4*)(g_h + (size_t)node * HIDDEN);
    float4 v0 = hn[lane];
    float4 v1 = hn[lane + 32];
    float4 acc0 = make_float4(v0.x * s2, v0.y * s2, v0.z * s2, v0.w * s2);
    float4 acc1 = make_float4(v1.x * s2, v1.y * s2, v1.z * s2, v1.w * s2);

    int beg = g_rowptr[node];
    int end = g_rowptr[node + 1];
#pragma unroll 4
    for (int e = beg; e < end; e++) {
        int   src = clamp_node(g_csr_src[e]);   // uniform across warp
        float nrm = g_csr_nrm[e];
        const float4* hs = (const float4*)(g_h + (size_t)src * HIDDEN);
        float4 a = hs[lane];
        float4 b = hs[lane + 32];
        acc0.x = fmaf(a.x, nrm, acc0.x);
        acc0.y = fmaf(a.y, nrm, acc0.y);
        acc0.z = fmaf(a.z, nrm, acc0.z);
        acc0.w = fmaf(a.w, nrm, acc0.w);
        acc1.x = fmaf(b.x, nrm, acc1.x);
        acc1.y = fmaf(b.y, nrm, acc1.y);
        acc1.z = fmaf(b.z, nrm, acc1.z);
        acc1.w = fmaf(b.w, nrm, acc1.w);
    }

    const float4* bp = (const float4*)bias;
    float4 bv0 = bp[lane];
    float4 bv1 = bp[lane + 32];
    acc0.x = fmaxf(acc0.x + bv0.x, 0.0f);
    acc0.y = fmaxf(acc0.y + bv0.y, 0.0f);
    acc0.z = fmaxf(acc0.z + bv0.z, 0.0f);
    acc0.w = fmaxf(acc0.w + bv0.w, 0.0f);
    acc1.x = fmaxf(acc1.x + bv1.x, 0.0f);
    acc1.y = fmaxf(acc1.y + bv1.y, 0.0f);
    acc1.z = fmaxf(acc1.z + bv1.z, 0.0f);
    acc1.w = fmaxf(acc1.w + bv1.w, 0.0f);

    float4* on = (float4*)(g_agg + (size_t)node * HIDDEN);
    on[lane]      = acc0;
    on[lane + 32] = acc1;
}

// ---------------------------------------------------------------------------
// fp32 SIMT GEMM: C[M,N] = A[M,K] @ B[K,N] (+bias). 128x128 tile, BK=16,
// 256 threads, 8x8 register tile. K multiple of 16.
// a_sel: 0 -> A = A_ext, 1 -> A = g_agg.  c_sel: 0 -> C = g_h, 1 -> C = C_ext
// ---------------------------------------------------------------------------
__global__ __launch_bounds__(256, 2)
void gnn3_gemm_kernel(const float* __restrict__ A_ext, int a_sel,
                      const float* __restrict__ B,
                      const float* __restrict__ bias, int has_bias,
                      float* __restrict__ C_ext, int c_sel,
                      int M, int N, int K) {
    const float* A = a_sel ? (const float*)g_agg : A_ext;
    float*       C = c_sel ? C_ext : (float*)g_h;

    __shared__ float As[16][128];   // [k][m]
    __shared__ float Bs[16][128];   // [k][n]

    int tid = threadIdx.x;
    int tx = tid & 15;
    int ty = tid >> 4;
    int m0 = blockIdx.x * 128;
    int n0 = blockIdx.y * 128;

    float c[8][8];
#pragma unroll
    for (int i = 0; i < 8; i++)
#pragma unroll
        for (int j = 0; j < 8; j++) c[i][j] = 0.0f;

    const int aRow = tid >> 1;           // 0..127
    const int aK   = (tid & 1) * 8;      // 0 or 8
    const int bK   = tid >> 4;           // 0..15
    const int bN   = (tid & 15) * 8;     // 0..120

    for (int kt = 0; kt < K; kt += 16) {
        {
            int gm = m0 + aRow;
            float4 a0 = make_float4(0.f, 0.f, 0.f, 0.f);
            float4 a1 = a0;
            if (gm < M) {
                const float* Ap = A + (size_t)gm * K + kt + aK;
                a0 = *(const float4*)Ap;
                a1 = *(const float4*)(Ap + 4);
            }
            As[aK + 0][aRow] = a0.x;
            As[aK + 1][aRow] = a0.y;
            As[aK + 2][aRow] = a0.z;
            As[aK + 3][aRow] = a0.w;
            As[aK + 4][aRow] = a1.x;
            As[aK + 5][aRow] = a1.y;
            As[aK + 6][aRow] = a1.z;
            As[aK + 7][aRow] = a1.w;
        }
        {
            int gn = n0 + bN;
            const float* Bp = B + (size_t)(kt + bK) * N + gn;
            if (gn + 7 < N) {
                *(float4*)&Bs[bK][bN]     = *(const float4*)Bp;
                *(float4*)&Bs[bK][bN + 4] = *(const float4*)(Bp + 4);
            } else {
#pragma unroll
                for (int j = 0; j < 8; j++)
                    Bs[bK][bN + j] = (gn + j < N) ? Bp[j] : 0.0f;
            }
        }
        __syncthreads();

#pragma unroll
        for (int k = 0; k < 16; k++) {
            float4 a0 = *(const float4*)&As[k][ty * 8];
            float4 a1 = *(const float4*)&As[k][ty * 8 + 4];
            float4 b0 = *(const float4*)&Bs[k][tx * 8];
            float4 b1 = *(const float4*)&Bs[k][tx * 8 + 4];
            float av[8] = {a0.x, a0.y, a0.z, a0.w, a1.x, a1.y, a1.z, a1.w};
            float bv[8] = {b0.x, b0.y, b0.z, b0.w, b1.x, b1.y, b1.z, b1.w};
#pragma unroll
            for (int i = 0; i < 8; i++)
#pragma unroll
                for (int j = 0; j < 8; j++)
                    c[i][j] = fmaf(av[i], bv[j], c[i][j]);
        }
        __syncthreads();
    }

#pragma unroll
    for (int i = 0; i < 8; i++) {
        int gm = m0 + ty * 8 + i;
        if (gm >= M) continue;
        float* Cp = C + (size_t)gm * N;
#pragma unroll
        for (int j = 0; j < 8; j++) {
            int gn = n0 + tx * 8 + j;
            if (gn < N) {
                float v = c[i][j];
                if (has_bias) v += bias[gn];
                Cp[gn] = v;
            }
        }
    }
}

// ---------------------------------------------------------------------------
// launch: kernel launches only
// ---------------------------------------------------------------------------
extern "C" void kernel_launch(void* const* d_in, const int* in_sizes, int n_in,
                              void* d_out, int out_size) {
    const float* x   = (const float*)d_in[0];
    const void*  ei  = d_in[1];                 // int32 OR int64, detected on device
    const float* W1  = (const float*)d_in[2];
    const float* b1  = (const float*)d_in[3];
    const float* W2  = (const float*)d_in[4];
    const float* b2  = (const float*)d_in[5];
    const float* Wfc = (const float*)d_in[6];
    const float* bfc = (const float*)d_in[7];
    float*       out = (float*)d_out;

    const int E = in_sizes[1] / 2;

    const int T = 256;
    const int nodeBlocks   = (N_NODES + T - 1) / T;
    const int edgeBlocks   = (E + T - 1) / T;
    const int gatherBlocks = (N_NODES + 7) / 8;   // 8 warps (nodes) per block

    // ---- dtype detect + CSR build + normalization ----
    gnn3_detect_kernel<<<1, 32>>>((const int*)ei);
    gnn3_init_kernel<<<nodeBlocks, T>>>();
    gnn3_count_kernel<<<edgeBlocks, T>>>(ei, E);
    gnn3_scan_kernel<<<1, 1024>>>();
    gnn3_dinv_kernel<<<nodeBlocks, T>>>();
    gnn3_fill_kernel<<<edgeBlocks, T>>>(ei, E);

    // ---- layer 1: g_h = x @ W1 ; g_agg = relu(A_norm g_h + b1) ----
    {
        dim3 grid((N_NODES + 127) / 128, (HIDDEN + 127) / 128);
        gnn3_gemm_kernel<<<grid, 256>>>(x, 0, W1, nullptr, 0, nullptr, 0,
                                        N_NODES, HIDDEN, IN_DIM);
    }
    gnn3_gather_kernel<<<gatherBlocks, T>>>(b1);

    // ---- layer 2: g_h = g_agg @ W2 ; g_agg = relu(A_norm g_h + b2) ----
    {
        dim3 grid((N_NODES + 127) / 128, (HIDDEN + 127) / 128);
        gnn3_gemm_kernel<<<grid, 256>>>(nullptr, 1, W2, nullptr, 0, nullptr, 0,
                                        N_NODES, HIDDEN, HIDDEN);
    }
    gnn3_gather_kernel<<<gatherBlocks, T>>>(b2);

    // ---- fc head: out = g_agg @ Wfc + bfc ----
    {
        dim3 grid((N_NODES + 127) / 128, (N_CLASSES + 127) / 128);
        gnn3_gemm_kernel<<<grid, 256>>>(nullptr, 1, Wfc, bfc, 1, out, 1,
                                        N_NODES, N_CLASSES, HIDDEN);
    }
}

// round 12
// speedup vs baseline: 1.1662x; 1.1662x over previous
#include <cuda_runtime.h>
#include <cuda_bf16.h>
#include <cstdint>

#define N_NODES   100000
#define MAX_EDGES 3400000
#define IN_DIM    512
#define HIDDEN    256
#define N_CLASSES 1000
#define NPAD_FC   1024

// ---------------------------------------------------------------------------
// Scratch: __device__ globals. RULE: never passed as host-side kernel args —
// always resolved inside kernels via selector ints (GB300 ATS makes the
// host-shadow-symbol bug silent instead of a crash; round-11 lesson).
// ---------------------------------------------------------------------------
__device__ int   g_is64;
__device__ int   g_bad[3];
__device__ int   g_cnt[N_NODES];
__device__ int   g_cursor[N_NODES];
__device__ int   g_rowptr[N_NODES + 1];
__device__ float g_dinv[N_NODES];
__device__ int   g_csr_src[MAX_EDGES];
__device__ float g_csr_nrm[MAX_EDGES];
__device__ __align__(16) float g_h[(size_t)N_NODES * HIDDEN];
__device__ __align__(16) float g_agg[(size_t)N_NODES * HIDDEN];
__device__ __align__(16) __nv_bfloat16 g_xhi[(size_t)N_NODES * IN_DIM];
__device__ __align__(16) __nv_bfloat16 g_xlo[(size_t)N_NODES * IN_DIM];
__device__ __align__(16) __nv_bfloat16 g_ahi[(size_t)N_NODES * HIDDEN];
__device__ __align__(16) __nv_bfloat16 g_alo[(size_t)N_NODES * HIDDEN];
__device__ __align__(16) __nv_bfloat16 g_w1hi[HIDDEN * IN_DIM];
__device__ __align__(16) __nv_bfloat16 g_w1lo[HIDDEN * IN_DIM];
__device__ __align__(16) __nv_bfloat16 g_w2hi[HIDDEN * HIDDEN];
__device__ __align__(16) __nv_bfloat16 g_w2lo[HIDDEN * HIDDEN];
__device__ __align__(16) __nv_bfloat16 g_wfhi[NPAD_FC * HIDDEN];
__device__ __align__(16) __nv_bfloat16 g_wflo[NPAD_FC * HIDDEN];

// ---------------------------------------------------------------------------
// helpers
// ---------------------------------------------------------------------------
__device__ __forceinline__ uint32_t smem_u32(const void* p) {
    uint32_t a;
    asm("{ .reg .u64 t; cvta.to.shared.u64 t, %1; cvt.u32.u64 %0, t; }"
        : "=r"(a) : "l"(p));
    return a;
}
__device__ __forceinline__ void split1(float v, __nv_bfloat16& h, __nv_bfloat16& l) {
    h = __float2bfloat16_rn(v);
    l = __float2bfloat16_rn(v - __bfloat162float(h));
}
__device__ __forceinline__ int edge_at(const void* ei, long long i) {
    if (g_is64) return (int)((const long long*)ei)[i];
    return ((const int*)ei)[i];
}
__device__ __forceinline__ int clamp_node(int v) {
    return (v < 0) ? 0 : (v >= N_NODES ? N_NODES - 1 : v);
}

// ---------------------------------------------------------------------------
// dtype detect + CSR build (round-8 proven versions)
// ---------------------------------------------------------------------------
__global__ void gnn7_detect_kernel(const int* __restrict__ ei32) {
    if (threadIdx.x == 0 && blockIdx.x == 0) {
        int nonzero = 0;
        for (int i = 0; i < 2048; i++)
            if (ei32[2 * i + 1] != 0) nonzero++;
        g_is64 = (nonzero == 0) ? 1 : 0;
    }
}

__global__ void gnn7_init_kernel() {
    int i = blockIdx.x * blockDim.x + threadIdx.x;
    if (i < N_NODES) { g_cnt[i] = 0; g_cursor[i] = 0; }
    if (i < 3) g_bad[i] = 0;
}

__global__ void gnn7_count_kernel(const void* __restrict__ ei, int E) {
    int e = blockIdx.x * blockDim.x + threadIdx.x;
    if (e < E) atomicAdd(&g_cnt[clamp_node(edge_at(ei, (long long)E + e))], 1);
}

// single-block scan (round-8 proven)
__global__ void gnn7_scan_kernel() {
    __shared__ int ssum[1024];
    const int t = threadIdx.x;
    const int CHUNK = (N_NODES + 1023) / 1024;
    int beg = t * CHUNK;
    int end = min(beg + CHUNK, N_NODES);
    int s = 0;
    for (int i = beg; i < end; i++) s += g_cnt[i];
    ssum[t] = s;
    __syncthreads();
    for (int off = 1; off < 1024; off <<= 1) {
        int v = 0;
        if (t >= off) v = ssum[t - off];
        __syncthreads();
        if (t >= off) ssum[t] += v;
        __syncthreads();
    }
    int run = (t == 0) ? 0 : ssum[t - 1];
    for (int i = beg; i < end; i++) {
        g_rowptr[i] = run;
        run += g_cnt[i];
    }
    if (t == 0) g_rowptr[N_NODES] = ssum[1023];
}

__global__ void gnn7_dinv_kernel() {
    int i = blockIdx.x * blockDim.x + threadIdx.x;
    if (i < N_NODES) g_dinv[i] = rsqrtf((float)g_cnt[i] + 1.0f);
}

__global__ void gnn7_fill_kernel(const void* __restrict__ ei, int E) {
    int e = blockIdx.x * blockDim.x + threadIdx.x;
    if (e >= E) return;
    int r = clamp_node(edge_at(ei, e));
    int c = clamp_node(edge_at(ei, (long long)E + e));
    int pos = atomicAdd(&g_cursor[c], 1);
    int idx = g_rowptr[c] + pos;
    if (idx >= 0 && idx < MAX_EDGES) {
        g_csr_src[idx] = r;
        g_csr_nrm[idx] = g_dinv[r] * g_dinv[c];
    }
}

// ---------------------------------------------------------------------------
// splits (globals resolved internally)
// ---------------------------------------------------------------------------
__global__ void gnn7_xsplit_kernel(const float* __restrict__ x) {
    int idx = blockIdx.x * blockDim.x + threadIdx.x;
    if (idx >= N_NODES * (IN_DIM / 4)) return;
    float4 v = ((const float4*)x)[idx];
    __nv_bfloat16 h0, h1, h2, h3, l0, l1, l2, l3;
    split1(v.x, h0, l0); split1(v.y, h1, l1);
    split1(v.z, h2, l2); split1(v.w, h3, l3);
    __nv_bfloat162 ph0; ph0.x = h0; ph0.y = h1;
    __nv_bfloat162 ph1; ph1.x = h2; ph1.y = h3;
    __nv_bfloat162 pl0; pl0.x = l0; pl0.y = l1;
    __nv_bfloat162 pl1; pl1.x = l2; pl1.y = l3;
    ((__nv_bfloat162*)g_xhi)[idx * 2]     = ph0;
    ((__nv_bfloat162*)g_xhi)[idx * 2 + 1] = ph1;
    ((__nv_bfloat162*)g_xlo)[idx * 2]     = pl0;
    ((__nv_bfloat162*)g_xlo)[idx * 2 + 1] = pl1;
}

// W [K][N] row-major -> Wt [Nout][K] K-major, split. slot: 0=W1, 1=W2, 2=Wfc
__global__ void gnn7_wsplit_kernel(const float* __restrict__ W, int K, int N,
                                   int Nout, int slot) {
    __nv_bfloat16* hi = (slot == 0) ? g_w1hi : (slot == 1) ? g_w2hi : g_wfhi;
    __nv_bfloat16* lo = (slot == 0) ? g_w1lo : (slot == 1) ? g_w2lo : g_wflo;
    int idx = blockIdx.x * blockDim.x + threadIdx.x;
    if (idx >= Nout * K) return;
    int n = idx / K, k = idx % K;
    float v = (n < N) ? W[(size_t)k * N + n] : 0.0f;
    __nv_bfloat16 h, l;
    split1(v, h, l);
    hi[idx] = h;
    lo[idx] = l;
}

// ---------------------------------------------------------------------------
// gather (round-8 proven + bf16 split emission)
// ---------------------------------------------------------------------------
__global__ __launch_bounds__(256)
void gnn7_gather_kernel(const float* __restrict__ bias) {
    int warp = (blockIdx.x * blockDim.x + threadIdx.x) >> 5;
    int lane = threadIdx.x & 31;
    if (warp >= N_NODES) return;
    const int node = warp;

    float s  = g_dinv[node];
    float s2 = s * s;

    const float4* hn = (const float4*)(g_h + (size_t)node * HIDDEN);
    float4 v0 = hn[lane];
    float4 v1 = hn[lane + 32];
    float4 acc0 = make_float4(v0.x * s2, v0.y * s2, v0.z * s2, v0.w * s2);
    float4 acc1 = make_float4(v1.x * s2, v1.y * s2, v1.z * s2, v1.w * s2);

    int beg = g_rowptr[node];
    int end = g_rowptr[node + 1];
#pragma unroll 4
    for (int e = beg; e < end; e++) {
        int   src = clamp_node(g_csr_src[e]);
        float nrm = g_csr_nrm[e];
        const float4* hs = (const float4*)(g_h + (size_t)src * HIDDEN);
        float4 a = hs[lane];
        float4 b = hs[lane + 32];
        acc0.x = fmaf(a.x, nrm, acc0.x);
        acc0.y = fmaf(a.y, nrm, acc0.y);
        acc0.z = fmaf(a.z, nrm, acc0.z);
        acc0.w = fmaf(a.w, nrm, acc0.w);
        acc1.x = fmaf(b.x, nrm, acc1.x);
        acc1.y = fmaf(b.y, nrm, acc1.y);
        acc1.z = fmaf(b.z, nrm, acc1.z);
        acc1.w = fmaf(b.w, nrm, acc1.w);
    }

    const float4* bp = (const float4*)bias;
    float4 bv0 = bp[lane];
    float4 bv1 = bp[lane + 32];
    acc0.x = fmaxf(acc0.x + bv0.x, 0.0f);
    acc0.y = fmaxf(acc0.y + bv0.y, 0.0f);
    acc0.z = fmaxf(acc0.z + bv0.z, 0.0f);
    acc0.w = fmaxf(acc0.w + bv0.w, 0.0f);
    acc1.x = fmaxf(acc1.x + bv1.x, 0.0f);
    acc1.y = fmaxf(acc1.y + bv1.y, 0.0f);
    acc1.z = fmaxf(acc1.z + bv1.z, 0.0f);
    acc1.w = fmaxf(acc1.w + bv1.w, 0.0f);

    float4* on = (float4*)(g_agg + (size_t)node * HIDDEN);
    on[lane]      = acc0;
    on[lane + 32] = acc1;

    size_t base = (size_t)node * HIDDEN;
    __nv_bfloat16 h0, h1, h2, h3, l0, l1, l2, l3;
    split1(acc0.x, h0, l0); split1(acc0.y, h1, l1);
    split1(acc0.z, h2, l2); split1(acc0.w, h3, l3);
    {
        __nv_bfloat162 a; a.x = h0; a.y = h1;
        __nv_bfloat162 b; b.x = h2; b.y = h3;
        __nv_bfloat162 c; c.x = l0; c.y = l1;
        __nv_bfloat162 d; d.x = l2; d.y = l3;
        ((__nv_bfloat162*)(g_ahi + base + 4 * lane))[0] = a;
        ((__nv_bfloat162*)(g_ahi + base + 4 * lane))[1] = b;
        ((__nv_bfloat162*)(g_alo + base + 4 * lane))[0] = c;
        ((__nv_bfloat162*)(g_alo + base + 4 * lane))[1] = d;
    }
    split1(acc1.x, h0, l0); split1(acc1.y, h1, l1);
    split1(acc1.z, h2, l2); split1(acc1.w, h3, l3);
    {
        __nv_bfloat162 a; a.x = h0; a.y = h1;
        __nv_bfloat162 b; b.x = h2; b.y = h3;
        __nv_bfloat162 c; c.x = l0; c.y = l1;
        __nv_bfloat162 d; d.x = l2; d.y = l3;
        ((__nv_bfloat162*)(g_ahi + base + 128 + 4 * lane))[0] = a;
        ((__nv_bfloat162*)(g_ahi + base + 128 + 4 * lane))[1] = b;
        ((__nv_bfloat162*)(g_alo + base + 128 + 4 * lane))[0] = c;
        ((__nv_bfloat162*)(g_alo + base + 128 + 4 * lane))[1] = d;
    }
}

// ---------------------------------------------------------------------------
// mma.sync split-bf16 GEMM. Operands resolved INSIDE via selectors.
// a_sel: 0 -> g_xhi/g_xlo, 1 -> g_ahi/g_alo.  b_sel: 0/1/2 -> W1/W2/Wfc.
// c_sel: 0 -> g_h, 1 -> Cext.
// ---------------------------------------------------------------------------
#define SMS 40

__device__ __forceinline__ void ldmx4(uint32_t* r, uint32_t addr) {
    asm volatile("ldmatrix.sync.aligned.m8n8.x4.shared.b16 {%0,%1,%2,%3}, [%4];"
                 : "=r"(r[0]), "=r"(r[1]), "=r"(r[2]), "=r"(r[3]) : "r"(addr));
}
__device__ __forceinline__ void mma16816(float* d, const uint32_t* a,
                                         uint32_t b0, uint32_t b1) {
    asm volatile(
        "mma.sync.aligned.m16n8k16.row.col.f32.bf16.bf16.f32 "
        "{%0,%1,%2,%3}, {%4,%5,%6,%7}, {%8,%9}, {%0,%1,%2,%3};"
        : "+f"(d[0]), "+f"(d[1]), "+f"(d[2]), "+f"(d[3])
        : "r"(a[0]), "r"(a[1]), "r"(a[2]), "r"(a[3]), "r"(b0), "r"(b1));
}

__global__ __launch_bounds__(256, 2)
void gnn7_mma_gemm(int a_sel, int b_sel,
                   const float* __restrict__ bias, int has_bias,
                   float* __restrict__ Cext, int c_sel,
                   int lda, int ldc, int M, int Nvalid, int K) {
    const __nv_bfloat16* Ahi = a_sel ? g_ahi : g_xhi;
    const __nv_bfloat16* Alo = a_sel ? g_alo : g_xlo;
    const __nv_bfloat16* Bhi = (b_sel == 0) ? g_w1hi : (b_sel == 1) ? g_w2hi : g_wfhi;
    const __nv_bfloat16* Blo = (b_sel == 0) ? g_w1lo : (b_sel == 1) ? g_w2lo : g_wflo;
    float* C = c_sel ? Cext : (float*)g_h;

    __shared__ __nv_bfloat16 sAh[128 * SMS];
    __shared__ __nv_bfloat16 sAl[128 * SMS];
    __shared__ __nv_bfloat16 sBh[128 * SMS];
    __shared__ __nv_bfloat16 sBl[128 * SMS];

    const int tid  = threadIdx.x;
    const int lane = tid & 31;
    const int wid  = tid >> 5;
    const int wm   = wid & 3;
    const int wn   = wid >> 2;
    const int m0   = blockIdx.x * 128;
    const int n0   = blockIdx.y * 128;

    float acc[2][8][4];
#pragma unroll
    for (int i = 0; i < 2; i++)
#pragma unroll
        for (int j = 0; j < 8; j++)
#pragma unroll
            for (int q = 0; q < 4; q++) acc[i][j][q] = 0.0f;

    const int a_r = (lane & 15);
    const int a_c = ((lane >> 4) << 3);
    const int b_r = (lane & 7) + ((lane >> 4) << 3);
    const int b_c = (((lane >> 3) & 1) << 3);

    for (int kb = 0; kb < K; kb += 32) {
#pragma unroll
        for (int j = tid; j < 512; j += 256) {
            int r = j >> 2, q = j & 3;
            int gm = m0 + r;
            uint4 vh = make_uint4(0u, 0u, 0u, 0u), vl = vh;
            if (gm < M) {
                vh = *(const uint4*)(Ahi + (size_t)gm * lda + kb + q * 8);
                vl = *(const uint4*)(Alo + (size_t)gm * lda + kb + q * 8);
            }
            *(uint4*)&sAh[r * SMS + q * 8] = vh;
            *(uint4*)&sAl[r * SMS + q * 8] = vl;
        }
#pragma unroll
        for (int j = tid; j < 512; j += 256) {
            int r = j >> 2, q = j & 3;
            *(uint4*)&sBh[r * SMS + q * 8] =
                *(const uint4*)(Bhi + (size_t)(n0 + r) * lda + kb + q * 8);
            *(uint4*)&sBl[r * SMS + q * 8] =
                *(const uint4*)(Blo + (size_t)(n0 + r) * lda + kb + q * 8);
        }
        __syncthreads();

#pragma unroll
        for (int ks = 0; ks < 32; ks += 16) {
#pragma unroll
            for (int pass = 0; pass < 3; pass++) {
                const __nv_bfloat16* tA = (pass == 1) ? sAl : sAh;
                const __nv_bfloat16* tB = (pass == 2) ? sBl : sBh;

                uint32_t a[2][4];
#pragma unroll
                for (int im = 0; im < 2; im++) {
                    int row = wm * 32 + im * 16 + a_r;
                    ldmx4(a[im], smem_u32(&tA[row * SMS + ks + a_c]));
                }
                uint32_t b[8][2];
#pragma unroll
                for (int p = 0; p < 4; p++) {
                    uint32_t r4[4];
                    int row = wn * 64 + p * 16 + b_r;
                    ldmx4(r4, smem_u32(&tB[row * SMS + ks + b_c]));
                    b[2 * p][0]     = r4[0];
                    b[2 * p][1]     = r4[1];
                    b[2 * p + 1][0] = r4[2];
                    b[2 * p + 1][1] = r4[3];
                }
#pragma unroll
                for (int im = 0; im < 2; im++)
#pragma unroll
                    for (int in = 0; in < 8; in++)
                        mma16816(acc[im][in], a[im], b[in][0], b[in][1]);
            }
        }
        __syncthreads();
    }

#pragma unroll
    for (int im = 0; im < 2; im++) {
        int r0 = m0 + wm * 32 + im * 16 + (lane >> 2);
        int r1 = r0 + 8;
#pragma unroll
        for (int in = 0; in < 8; in++) {
            int gn = n0 + wn * 64 + in * 8 + (lane & 3) * 2;
            if (gn >= Nvalid) continue;
            float bx = 0.f, by = 0.f;
            if (has_bias) {
                float2 bb = *(const float2*)(bias + gn);
                bx = bb.x; by = bb.y;
            }
            if (r0 < M) {
                float2 v; v.x = acc[im][in][0] + bx; v.y = acc[im][in][1] + by;
                *(float2*)(C + (size_t)r0 * ldc + gn) = v;
            }
            if (r1 < M) {
                float2 v; v.x = acc[im][in][2] + bx; v.y = acc[im][in][3] + by;
                *(float2*)(C + (size_t)r1 * ldc + gn) = v;
            }
        }
    }
}

// ---------------------------------------------------------------------------
// validation: 256 fp32-recomputed samples vs GEMM output; sets g_bad[slot]
// ---------------------------------------------------------------------------
__global__ void gnn7_validate_kernel(const float* __restrict__ Aext, int a_sel,
                                     const float* __restrict__ W,
                                     const float* __restrict__ bias, int has_bias,
                                     const float* __restrict__ Cext, int c_sel,
                                     int M, int N, int K, int slot) {
    const float* A = a_sel ? (const float*)g_agg : Aext;
    const float* C = c_sel ? Cext : (const float*)g_h;
    int t = threadIdx.x;
    unsigned m = (2654435761u * (unsigned)(t + 3)) % (unsigned)M;
    unsigned n = (40503u * (unsigned)(t + 7) + 9973u) % (unsigned)N;
    float ref = 0.0f;
    const float* Ar = A + (size_t)m * K;
    for (int k = 0; k < K; k++) ref = fmaf(Ar[k], W[(size_t)k * N + n], ref);
    if (has_bias) ref += bias[n];
    float got = C[(size_t)m * N + n];
    float err = fabsf(got - ref) / fmaxf(fabsf(ref), 1.0f);
    if (err > 2e-3f) g_bad[slot] = 1;
}

// ---------------------------------------------------------------------------
// fallback fp32 SIMT GEMM (round-8 proven) — runs only if g_bad[slot]
// ---------------------------------------------------------------------------
__global__ __launch_bounds__(256, 2)
void gnn7_fallback_gemm(const float* __restrict__ A_ext, int a_sel,
                        const float* __restrict__ B,
                        const float* __restrict__ bias, int has_bias,
                        float* __restrict__ C_ext, int c_sel,
                        int M, int N, int K, int slot) {
    if (g_bad[slot] == 0) return;
    const float* A = a_sel ? (const float*)g_agg : A_ext;
    float*       C = c_sel ? C_ext : (float*)g_h;

    __shared__ float As[16][128];
    __shared__ float Bs[16][128];

    int tid = threadIdx.x;
    int tx = tid & 15;
    int ty = tid >> 4;
    int m0 = blockIdx.x * 128;
    int n0 = blockIdx.y * 128;

    float c[8][8];
#pragma unroll
    for (int i = 0; i < 8; i++)
#pragma unroll
        for (int j = 0; j < 8; j++) c[i][j] = 0.0f;

    const int aRow = tid >> 1;
    const int aK   = (tid & 1) * 8;
    const int bK   = tid >> 4;
    const int bN   = (tid & 15) * 8;

    for (int kt = 0; kt < K; kt += 16) {
        {
            int gm = m0 + aRow;
            float4 a0 = make_float4(0.f, 0.f, 0.f, 0.f);
            float4 a1 = a0;
            if (gm < M) {
                const float* Ap = A + (size_t)gm * K + kt + aK;
                a0 = *(const float4*)Ap;
                a1 = *(const float4*)(Ap + 4);
            }
            As[aK + 0][aRow] = a0.x;
            As[aK + 1][aRow] = a0.y;
            As[aK + 2][aRow] = a0.z;
            As[aK + 3][aRow] = a0.w;
            As[aK + 4][aRow] = a1.x;
            As[aK + 5][aRow] = a1.y;
            As[aK + 6][aRow] = a1.z;
            As[aK + 7][aRow] = a1.w;
        }
        {
            int gn = n0 + bN;
            const float* Bp = B + (size_t)(kt + bK) * N + gn;
            if (gn + 7 < N) {
                *(float4*)&Bs[bK][bN]     = *(const float4*)Bp;
                *(float4*)&Bs[bK][bN + 4] = *(const float4*)(Bp + 4);
            } else {
#pragma unroll
                for (int j = 0; j < 8; j++)
                    Bs[bK][bN + j] = (gn + j < N) ? Bp[j] : 0.0f;
            }
        }
        __syncthreads();

#pragma unroll
        for (int k = 0; k < 16; k++) {
            float4 a0 = *(const float4*)&As[k][ty * 8];
            float4 a1 = *(const float4*)&As[k][ty * 8 + 4];
            float4 b0 = *(const float4*)&Bs[k][tx * 8];
            float4 b1 = *(const float4*)&Bs[k][tx * 8 + 4];
            float av[8] = {a0.x, a0.y, a0.z, a0.w, a1.x, a1.y, a1.z, a1.w};
            float bv[8] = {b0.x, b0.y, b0.z, b0.w, b1.x, b1.y, b1.z, b1.w};
#pragma unroll
            for (int i = 0; i < 8; i++)
#pragma unroll
                for (int j = 0; j < 8; j++)
                    c[i][j] = fmaf(av[i], bv[j], c[i][j]);
        }
        __syncthreads();
    }

#pragma unroll
    for (int i = 0; i < 8; i++) {
        int gm = m0 + ty * 8 + i;
        if (gm >= M) continue;
        float* Cp = C + (size_t)gm * N;
#pragma unroll
        for (int j = 0; j < 8; j++) {
            int gn = n0 + tx * 8 + j;
            if (gn < N) {
                float v = c[i][j];
                if (has_bias) v += bias[gn];
                Cp[gn] = v;
            }
        }
    }
}

// ---------------------------------------------------------------------------
// launch
// ---------------------------------------------------------------------------
extern "C" void kernel_launch(void* const* d_in, const int* in_sizes, int n_in,
                              void* d_out, int out_size) {
    const float* x   = (const float*)d_in[0];
    const void*  ei  = d_in[1];
    const float* W1  = (const float*)d_in[2];
    const float* b1  = (const float*)d_in[3];
    const float* W2  = (const float*)d_in[4];
    const float* b2  = (const float*)d_in[5];
    const float* Wfc = (const float*)d_in[6];
    const float* bfc = (const float*)d_in[7];
    float*       out = (float*)d_out;

    const int E = in_sizes[1] / 2;

    const int T = 256;
    const int nodeBlocks   = (N_NODES + T - 1) / T;
    const int edgeBlocks   = (E + T - 1) / T;
    const int gatherBlocks = (N_NODES + 7) / 8;
    const int mBlocks      = (N_NODES + 127) / 128;   // 782

    // ---- dtype detect + CSR build (proven path) ----
    gnn7_detect_kernel<<<1, 32>>>((const int*)ei);
    gnn7_init_kernel<<<nodeBlocks, T>>>();
    gnn7_count_kernel<<<edgeBlocks, T>>>(ei, E);
    gnn7_scan_kernel<<<1, 1024>>>();
    gnn7_dinv_kernel<<<nodeBlocks, T>>>();
    gnn7_fill_kernel<<<edgeBlocks, T>>>(ei, E);

    // ---- operand prep ----
    gnn7_xsplit_kernel<<<(N_NODES * (IN_DIM / 4) + T - 1) / T, T>>>(x);
    gnn7_wsplit_kernel<<<(HIDDEN * IN_DIM + T - 1) / T, T>>>(W1, IN_DIM, HIDDEN, HIDDEN, 0);
    gnn7_wsplit_kernel<<<(HIDDEN * HIDDEN + T - 1) / T, T>>>(W2, HIDDEN, HIDDEN, HIDDEN, 1);
    gnn7_wsplit_kernel<<<(NPAD_FC * HIDDEN + T - 1) / T, T>>>(Wfc, HIDDEN, N_CLASSES, NPAD_FC, 2);

    // ---- layer 1 ----
    {
        dim3 grid(mBlocks, HIDDEN / 128);
        gnn7_mma_gemm<<<grid, 256>>>(0, 0, nullptr, 0, nullptr, 0,
                                     IN_DIM, HIDDEN, N_NODES, HIDDEN, IN_DIM);
        gnn7_validate_kernel<<<1, 256>>>(x, 0, W1, nullptr, 0, nullptr, 0,
                                         N_NODES, HIDDEN, IN_DIM, 0);
        dim3 fgrid(mBlocks, (HIDDEN + 127) / 128);
        gnn7_fallback_gemm<<<fgrid, 256>>>(x, 0, W1, nullptr, 0, nullptr, 0,
                                           N_NODES, HIDDEN, IN_DIM, 0);
    }
    gnn7_gather_kernel<<<gatherBlocks, T>>>(b1);

    // ---- layer 2 ----
    {
        dim3 grid(mBlocks, HIDDEN / 128);
        gnn7_mma_gemm<<<grid, 256>>>(1, 1, nullptr, 0, nullptr, 0,
                                     HIDDEN, HIDDEN, N_NODES, HIDDEN, HIDDEN);
        gnn7_validate_kernel<<<1, 256>>>(nullptr, 1, W2, nullptr, 0, nullptr, 0,
                                         N_NODES, HIDDEN, HIDDEN, 1);
        dim3 fgrid(mBlocks, (HIDDEN + 127) / 128);
        gnn7_fallback_gemm<<<fgrid, 256>>>(nullptr, 1, W2, nullptr, 0, nullptr, 0,
                                           N_NODES, HIDDEN, HIDDEN, 1);
    }
    gnn7_gather_kernel<<<gatherBlocks, T>>>(b2);

    // ---- fc head ----
    {
        dim3 grid(mBlocks, NPAD_FC / 128);
        gnn7_mma_gemm<<<grid, 256>>>(1, 2, bfc, 1, out, 1,
                                     HIDDEN, N_CLASSES, N_NODES, N_CLASSES, HIDDEN);
        gnn7_validate_kernel<<<1, 256>>>(nullptr, 1, Wfc, bfc, 1, out, 1,
                                         N_NODES, N_CLASSES, HIDDEN, 2);
        dim3 fgrid(mBlocks, (N_CLASSES + 127) / 128);
        gnn7_fallback_gemm<<<fgrid, 256>>>(nullptr, 1, Wfc, bfc, 1, out, 1,
                                           N_NODES, N_CLASSES, HIDDEN, 2);
    }
}

// round 13
// speedup vs baseline: 2.1830x; 1.8718x over previous
#include <cuda_runtime.h>
#include <cuda_bf16.h>
#include <cstdint>

#define N_NODES   100000
#define MAX_EDGES 3400000
#define IN_DIM    512
#define HIDDEN    256
#define N_CLASSES 1000
#define NPAD_FC   1024
#define SCAN_NB   98

// ---------------------------------------------------------------------------
// Scratch: __device__ globals. RULE: never passed as host-side kernel args —
// resolved inside kernels via selector ints (GB300 ATS makes the
// host-shadow-symbol bug silent instead of a crash; round-11 lesson).
// ---------------------------------------------------------------------------
__device__ int   g_is64;
__device__ int   g_cnt[N_NODES];
__device__ int   g_cursor[N_NODES];
__device__ int   g_rowptr[N_NODES + 1];
__device__ float g_dinv[N_NODES];
__device__ int   g_csr_src[MAX_EDGES];
__device__ float g_csr_nrm[MAX_EDGES];
__device__ int   g_bsum[SCAN_NB];
__device__ int   g_boff[SCAN_NB];
__device__ __align__(16) float g_h[(size_t)N_NODES * HIDDEN];
__device__ __align__(16) __nv_bfloat16 g_xhi[(size_t)N_NODES * IN_DIM];
__device__ __align__(16) __nv_bfloat16 g_xlo[(size_t)N_NODES * IN_DIM];
__device__ __align__(16) __nv_bfloat16 g_ahi[(size_t)N_NODES * HIDDEN];
__device__ __align__(16) __nv_bfloat16 g_alo[(size_t)N_NODES * HIDDEN];
__device__ __align__(16) __nv_bfloat16 g_w1hi[HIDDEN * IN_DIM];
__device__ __align__(16) __nv_bfloat16 g_w1lo[HIDDEN * IN_DIM];
__device__ __align__(16) __nv_bfloat16 g_w2hi[HIDDEN * HIDDEN];
__device__ __align__(16) __nv_bfloat16 g_w2lo[HIDDEN * HIDDEN];
__device__ __align__(16) __nv_bfloat16 g_wfhi[NPAD_FC * HIDDEN];
__device__ __align__(16) __nv_bfloat16 g_wflo[NPAD_FC * HIDDEN];

// ---------------------------------------------------------------------------
// helpers
// ---------------------------------------------------------------------------
__device__ __forceinline__ uint32_t smem_u32(const void* p) {
    uint32_t a;
    asm("{ .reg .u64 t; cvta.to.shared.u64 t, %1; cvt.u32.u64 %0, t; }"
        : "=r"(a) : "l"(p));
    return a;
}
__device__ __forceinline__ void split1(float v, __nv_bfloat16& h, __nv_bfloat16& l) {
    h = __float2bfloat16_rn(v);
    l = __float2bfloat16_rn(v - __bfloat162float(h));
}
__device__ __forceinline__ int edge_at(const void* ei, long long i) {
    if (g_is64) return (int)((const long long*)ei)[i];
    return ((const int*)ei)[i];
}
__device__ __forceinline__ int clamp_node(int v) {
    return (v < 0) ? 0 : (v >= N_NODES ? N_NODES - 1 : v);
}

// cp.async (sm_80 baseline — safe on compute_103). src-size 0 => zero-fill.
#define CPA16(s, g, p) \
    asm volatile("cp.async.cg.shared.global [%0], [%1], 16, %2;" \
                 :: "r"(s), "l"(g), "r"((p) ? 16 : 0))
#define CPA_COMMIT() asm volatile("cp.async.commit_group;" ::: "memory")
#define CPA_WAIT(n)  asm volatile("cp.async.wait_group %0;" :: "n"(n) : "memory")

// ---------------------------------------------------------------------------
// dtype detect (parallel)
// ---------------------------------------------------------------------------
__global__ void gnn8_detect_kernel(const int* __restrict__ ei32) {
    int t = threadIdx.x;
    int nz = 0;
    for (int i = t; i < 2048; i += 1024)
        if (ei32[2 * i + 1] != 0) nz = 1;
    int total = __syncthreads_count(nz);
    if (t == 0) g_is64 = (total == 0) ? 1 : 0;
}

// ---------------------------------------------------------------------------
// CSR build
// ---------------------------------------------------------------------------
__global__ void gnn8_init_kernel() {
    int i = blockIdx.x * blockDim.x + threadIdx.x;
    if (i < N_NODES) { g_cnt[i] = 0; g_cursor[i] = 0; }
}

__global__ void gnn8_count_kernel(const void* __restrict__ ei, int E) {
    int e = blockIdx.x * blockDim.x + threadIdx.x;
    if (e < E) atomicAdd(&g_cnt[clamp_node(edge_at(ei, (long long)E + e))], 1);
}

// coalesced 3-phase scan
__global__ void gnn8_scanA_kernel() {
    __shared__ int wsum[32];
    int i = blockIdx.x * 1024 + threadIdx.x;
    int v = (i < N_NODES) ? g_cnt[i] : 0;
    int s = v;
    for (int o = 16; o > 0; o >>= 1) s += __shfl_down_sync(0xFFFFFFFF, s, o);
    if ((threadIdx.x & 31) == 0) wsum[threadIdx.x >> 5] = s;
    __syncthreads();
    if (threadIdx.x < 32) {
        int t = (threadIdx.x < 32) ? wsum[threadIdx.x] : 0;
        for (int o = 16; o > 0; o >>= 1) t += __shfl_down_sync(0xFFFFFFFF, t, o);
        if (threadIdx.x == 0) g_bsum[blockIdx.x] = t;
    }
}

__global__ void gnn8_scanB_kernel() {
    if (threadIdx.x == 0) {
        int run = 0;
        for (int i = 0; i < SCAN_NB; i++) { g_boff[i] = run; run += g_bsum[i]; }
    }
}

__global__ void gnn8_scanC_kernel() {
    __shared__ int s[1024];
    int t = threadIdx.x;
    int i = blockIdx.x * 1024 + t;
    int v = (i < N_NODES) ? g_cnt[i] : 0;
    s[t] = v;
    __syncthreads();
    for (int off = 1; off < 1024; off <<= 1) {
        int add = (t >= off) ? s[t - off] : 0;
        __syncthreads();
        s[t] += add;
        __syncthreads();
    }
    int excl = s[t] - v + g_boff[blockIdx.x];
    if (i < N_NODES) {
        g_rowptr[i] = excl;
        if (i == N_NODES - 1) g_rowptr[N_NODES] = excl + v;
    }
}

__global__ void gnn8_dinv_kernel() {
    int i = blockIdx.x * blockDim.x + threadIdx.x;
    if (i < N_NODES) g_dinv[i] = rsqrtf((float)g_cnt[i] + 1.0f);
}

__global__ void gnn8_fill_kernel(const void* __restrict__ ei, int E) {
    int e = blockIdx.x * blockDim.x + threadIdx.x;
    if (e >= E) return;
    int r = clamp_node(edge_at(ei, e));
    int c = clamp_node(edge_at(ei, (long long)E + e));
    int pos = atomicAdd(&g_cursor[c], 1);
    int idx = g_rowptr[c] + pos;
    if (idx >= 0 && idx < MAX_EDGES) {
        g_csr_src[idx] = r;
        g_csr_nrm[idx] = g_dinv[r] * g_dinv[c];
    }
}

// ---------------------------------------------------------------------------
// splits
// ---------------------------------------------------------------------------
__global__ void gnn8_xsplit_kernel(const float* __restrict__ x) {
    int idx = blockIdx.x * blockDim.x + threadIdx.x;
    if (idx >= N_NODES * (IN_DIM / 4)) return;
    float4 v = ((const float4*)x)[idx];
    __nv_bfloat16 h0, h1, h2, h3, l0, l1, l2, l3;
    split1(v.x, h0, l0); split1(v.y, h1, l1);
    split1(v.z, h2, l2); split1(v.w, h3, l3);
    __nv_bfloat162 ph0; ph0.x = h0; ph0.y = h1;
    __nv_bfloat162 ph1; ph1.x = h2; ph1.y = h3;
    __nv_bfloat162 pl0; pl0.x = l0; pl0.y = l1;
    __nv_bfloat162 pl1; pl1.x = l2; pl1.y = l3;
    ((__nv_bfloat162*)g_xhi)[idx * 2]     = ph0;
    ((__nv_bfloat162*)g_xhi)[idx * 2 + 1] = ph1;
    ((__nv_bfloat162*)g_xlo)[idx * 2]     = pl0;
    ((__nv_bfloat162*)g_xlo)[idx * 2 + 1] = pl1;
}

__global__ void gnn8_wsplit_kernel(const float* __restrict__ W, int K, int N,
                                   int Nout, int slot) {
    __nv_bfloat16* hi = (slot == 0) ? g_w1hi : (slot == 1) ? g_w2hi : g_wfhi;
    __nv_bfloat16* lo = (slot == 0) ? g_w1lo : (slot == 1) ? g_w2lo : g_wflo;
    int idx = blockIdx.x * blockDim.x + threadIdx.x;
    if (idx >= Nout * K) return;
    int n = idx / K, k = idx % K;
    float v = (n < N) ? W[(size_t)k * N + n] : 0.0f;
    __nv_bfloat16 h, l;
    split1(v, h, l);
    hi[idx] = h;
    lo[idx] = l;
}

// ---------------------------------------------------------------------------
// gather: one warp per node; emits ONLY bf16 hi/lo splits (fp32 agg dropped —
// nothing consumes it since validation removal).
// ---------------------------------------------------------------------------
__global__ __launch_bounds__(256)
void gnn8_gather_kernel(const float* __restrict__ bias) {
    int warp = (blockIdx.x * blockDim.x + threadIdx.x) >> 5;
    int lane = threadIdx.x & 31;
    if (warp >= N_NODES) return;
    const int node = warp;

    float s  = g_dinv[node];
    float s2 = s * s;

    const float4* hn = (const float4*)(g_h + (size_t)node * HIDDEN);
    float4 v0 = hn[lane];
    float4 v1 = hn[lane + 32];
    float4 acc0 = make_float4(v0.x * s2, v0.y * s2, v0.z * s2, v0.w * s2);
    float4 acc1 = make_float4(v1.x * s2, v1.y * s2, v1.z * s2, v1.w * s2);

    int beg = g_rowptr[node];
    int end = g_rowptr[node + 1];
#pragma unroll 4
    for (int e = beg; e < end; e++) {
        int   src = clamp_node(g_csr_src[e]);
        float nrm = g_csr_nrm[e];
        const float4* hs = (const float4*)(g_h + (size_t)src * HIDDEN);
        float4 a = hs[lane];
        float4 b = hs[lane + 32];
        acc0.x = fmaf(a.x, nrm, acc0.x);
        acc0.y = fmaf(a.y, nrm, acc0.y);
        acc0.z = fmaf(a.z, nrm, acc0.z);
        acc0.w = fmaf(a.w, nrm, acc0.w);
        acc1.x = fmaf(b.x, nrm, acc1.x);
        acc1.y = fmaf(b.y, nrm, acc1.y);
        acc1.z = fmaf(b.z, nrm, acc1.z);
        acc1.w = fmaf(b.w, nrm, acc1.w);
    }

    const float4* bp = (const float4*)bias;
    float4 bv0 = bp[lane];
    float4 bv1 = bp[lane + 32];
    acc0.x = fmaxf(acc0.x + bv0.x, 0.0f);
    acc0.y = fmaxf(acc0.y + bv0.y, 0.0f);
    acc0.z = fmaxf(acc0.z + bv0.z, 0.0f);
    acc0.w = fmaxf(acc0.w + bv0.w, 0.0f);
    acc1.x = fmaxf(acc1.x + bv1.x, 0.0f);
    acc1.y = fmaxf(acc1.y + bv1.y, 0.0f);
    acc1.z = fmaxf(acc1.z + bv1.z, 0.0f);
    acc1.w = fmaxf(acc1.w + bv1.w, 0.0f);

    size_t base = (size_t)node * HIDDEN;
    __nv_bfloat16 h0, h1, h2, h3, l0, l1, l2, l3;
    split1(acc0.x, h0, l0); split1(acc0.y, h1, l1);
    split1(acc0.z, h2, l2); split1(acc0.w, h3, l3);
    {
        __nv_bfloat162 a; a.x = h0; a.y = h1;
        __nv_bfloat162 b; b.x = h2; b.y = h3;
        __nv_bfloat162 c; c.x = l0; c.y = l1;
        __nv_bfloat162 d; d.x = l2; d.y = l3;
        ((__nv_bfloat162*)(g_ahi + base + 4 * lane))[0] = a;
        ((__nv_bfloat162*)(g_ahi + base + 4 * lane))[1] = b;
        ((__nv_bfloat162*)(g_alo + base + 4 * lane))[0] = c;
        ((__nv_bfloat162*)(g_alo + base + 4 * lane))[1] = d;
    }
    split1(acc1.x, h0, l0); split1(acc1.y, h1, l1);
    split1(acc1.z, h2, l2); split1(acc1.w, h3, l3);
    {
        __nv_bfloat162 a; a.x = h0; a.y = h1;
        __nv_bfloat162 b; b.x = h2; b.y = h3;
        __nv_bfloat162 c; c.x = l0; c.y = l1;
        __nv_bfloat162 d; d.x = l2; d.y = l3;
        ((__nv_bfloat162*)(g_ahi + base + 128 + 4 * lane))[0] = a;
        ((__nv_bfloat162*)(g_ahi + base + 128 + 4 * lane))[1] = b;
        ((__nv_bfloat162*)(g_alo + base + 128 + 4 * lane))[0] = c;
        ((__nv_bfloat162*)(g_alo + base + 128 + 4 * lane))[1] = d;
    }
}

// ---------------------------------------------------------------------------
// mma.sync split-bf16 GEMM, cp.async double-buffered.
// a_sel: 0 -> g_xhi/g_xlo, 1 -> g_ahi/g_alo.  b_sel: 0/1/2 -> W1/W2/Wfc.
// c_sel: 0 -> g_h, 1 -> Cext.
// dyn smem: 2 buffers x (Ah,Al,Bh,Bl) x 128*SMS bf16 = 81920 B.
// ---------------------------------------------------------------------------
#define SMS 40
#define TILE_B (128 * SMS * 2)            // bytes per tile (10240)
#define BUF_B  (4 * TILE_B)               // bytes per buffer set (40960)

__device__ __forceinline__ void ldmx4(uint32_t* r, uint32_t addr) {
    asm volatile("ldmatrix.sync.aligned.m8n8.x4.shared.b16 {%0,%1,%2,%3}, [%4];"
                 : "=r"(r[0]), "=r"(r[1]), "=r"(r[2]), "=r"(r[3]) : "r"(addr));
}
__device__ __forceinline__ void mma16816(float* d, const uint32_t* a,
                                         uint32_t b0, uint32_t b1) {
    asm volatile(
        "mma.sync.aligned.m16n8k16.row.col.f32.bf16.bf16.f32 "
        "{%0,%1,%2,%3}, {%4,%5,%6,%7}, {%8,%9}, {%0,%1,%2,%3};"
        : "+f"(d[0]), "+f"(d[1]), "+f"(d[2]), "+f"(d[3])
        : "r"(a[0]), "r"(a[1]), "r"(a[2]), "r"(a[3]), "r"(b0), "r"(b1));
}

__global__ __launch_bounds__(256, 2)
void gnn8_mma_gemm(int a_sel, int b_sel,
                   const float* __restrict__ bias, int has_bias,
                   float* __restrict__ Cext, int c_sel,
                   int lda, int ldc, int M, int Nvalid, int K) {
    const __nv_bfloat16* Ahi = a_sel ? g_ahi : g_xhi;
    const __nv_bfloat16* Alo = a_sel ? g_alo : g_xlo;
    const __nv_bfloat16* Bhi = (b_sel == 0) ? g_w1hi : (b_sel == 1) ? g_w2hi : g_wfhi;
    const __nv_bfloat16* Blo = (b_sel == 0) ? g_w1lo : (b_sel == 1) ? g_w2lo : g_wflo;
    float* C = c_sel ? Cext : (float*)g_h;

    extern __shared__ char dsm[];

    const int tid  = threadIdx.x;
    const int lane = tid & 31;
    const int wid  = tid >> 5;
    const int wm   = wid & 3;
    const int wn   = wid >> 2;
    const int m0   = blockIdx.x * 128;
    const int n0   = blockIdx.y * 128;

    float acc[2][8][4];
#pragma unroll
    for (int i = 0; i < 2; i++)
#pragma unroll
        for (int j = 0; j < 8; j++)
#pragma unroll
            for (int q = 0; q < 4; q++) acc[i][j][q] = 0.0f;

    const int a_r = (lane & 15);
    const int a_c = ((lane >> 4) << 3);
    const int b_r = (lane & 7) + ((lane >> 4) << 3);
    const int b_c = (((lane >> 3) & 1) << 3);

    // stage one K-chunk into buffer `buf` via cp.async (+commit)
    auto stage = [&](int buf, int kb) {
        char* base = dsm + buf * BUF_B;
        __nv_bfloat16* sAh = (__nv_bfloat16*)(base);
        __nv_bfloat16* sAl = (__nv_bfloat16*)(base + TILE_B);
        __nv_bfloat16* sBh = (__nv_bfloat16*)(base + 2 * TILE_B);
        __nv_bfloat16* sBl = (__nv_bfloat16*)(base + 3 * TILE_B);
#pragma unroll
        for (int j = tid; j < 512; j += 256) {
            int r = j >> 2, q = j & 3;
            int gm = m0 + r;
            bool p = gm < M;
            int gmc = p ? gm : (M - 1);
            const __nv_bfloat16* ph = Ahi + (size_t)gmc * lda + kb + q * 8;
            const __nv_bfloat16* pl = Alo + (size_t)gmc * lda + kb + q * 8;
            CPA16(smem_u32(&sAh[r * SMS + q * 8]), ph, p);
            CPA16(smem_u32(&sAl[r * SMS + q * 8]), pl, p);
        }
#pragma unroll
        for (int j = tid; j < 512; j += 256) {
            int r = j >> 2, q = j & 3;
            const __nv_bfloat16* ph = Bhi + (size_t)(n0 + r) * lda + kb + q * 8;
            const __nv_bfloat16* pl = Blo + (size_t)(n0 + r) * lda + kb + q * 8;
            CPA16(smem_u32(&sBh[r * SMS + q * 8]), ph, true);
            CPA16(smem_u32(&sBl[r * SMS + q * 8]), pl, true);
        }
        CPA_COMMIT();
    };

    const int nk = K >> 5;   // chunks of 32
    stage(0, 0);

    for (int kc = 0; kc < nk; kc++) {
        const int buf = kc & 1;
        if (kc + 1 < nk) {
            stage(buf ^ 1, (kc + 1) << 5);
            CPA_WAIT(1);
        } else {
            CPA_WAIT(0);
        }
        __syncthreads();

        char* base = dsm + buf * BUF_B;
        __nv_bfloat16* sAh = (__nv_bfloat16*)(base);
        __nv_bfloat16* sAl = (__nv_bfloat16*)(base + TILE_B);
        __nv_bfloat16* sBh = (__nv_bfloat16*)(base + 2 * TILE_B);
        __nv_bfloat16* sBl = (__nv_bfloat16*)(base + 3 * TILE_B);

#pragma unroll
        for (int ks = 0; ks < 32; ks += 16) {
#pragma unroll
            for (int pass = 0; pass < 3; pass++) {
                const __nv_bfloat16* tA = (pass == 1) ? sAl : sAh;
                const __nv_bfloat16* tB = (pass == 2) ? sBl : sBh;

                uint32_t a[2][4];
#pragma unroll
                for (int im = 0; im < 2; im++) {
                    int row = wm * 32 + im * 16 + a_r;
                    ldmx4(a[im], smem_u32(&tA[row * SMS + ks + a_c]));
                }
                uint32_t b[8][2];
#pragma unroll
                for (int p = 0; p < 4; p++) {
                    uint32_t r4[4];
                    int row = wn * 64 + p * 16 + b_r;
                    ldmx4(r4, smem_u32(&tB[row * SMS + ks + b_c]));
                    b[2 * p][0]     = r4[0];
                    b[2 * p][1]     = r4[1];
                    b[2 * p + 1][0] = r4[2];
                    b[2 * p + 1][1] = r4[3];
                }
#pragma unroll
                for (int im = 0; im < 2; im++)
#pragma unroll
                    for (int in = 0; in < 8; in++)
                        mma16816(acc[im][in], a[im], b[in][0], b[in][1]);
            }
        }
        __syncthreads();
    }

#pragma unroll
    for (int im = 0; im < 2; im++) {
        int r0 = m0 + wm * 32 + im * 16 + (lane >> 2);
        int r1 = r0 + 8;
#pragma unroll
        for (int in = 0; in < 8; in++) {
            int gn = n0 + wn * 64 + in * 8 + (lane & 3) * 2;
            if (gn >= Nvalid) continue;
            float bx = 0.f, by = 0.f;
            if (has_bias) {
                float2 bb = *(const float2*)(bias + gn);
                bx = bb.x; by = bb.y;
            }
            if (r0 < M) {
                float2 v; v.x = acc[im][in][0] + bx; v.y = acc[im][in][1] + by;
                *(float2*)(C + (size_t)r0 * ldc + gn) = v;
            }
            if (r1 < M) {
                float2 v; v.x = acc[im][in][2] + bx; v.y = acc[im][in][3] + by;
                *(float2*)(C + (size_t)r1 * ldc + gn) = v;
            }
        }
    }
}

// ---------------------------------------------------------------------------
// launch
// ---------------------------------------------------------------------------
extern "C" void kernel_launch(void* const* d_in, const int* in_sizes, int n_in,
                              void* d_out, int out_size) {
    const float* x   = (const float*)d_in[0];
    const void*  ei  = d_in[1];
    const float* W1  = (const float*)d_in[2];
    const float* b1  = (const float*)d_in[3];
    const float* W2  = (const float*)d_in[4];
    const float* b2  = (const float*)d_in[5];
    const float* Wfc = (const float*)d_in[6];
    const float* bfc = (const float*)d_in[7];
    float*       out = (float*)d_out;

    const int E = in_sizes[1] / 2;

    const int T = 256;
    const int nodeBlocks   = (N_NODES + T - 1) / T;
    const int edgeBlocks   = (E + T - 1) / T;
    const int gatherBlocks = (N_NODES + 7) / 8;
    const int mBlocks      = (N_NODES + 127) / 128;   // 782
    const int GEMM_SMEM    = 2 * BUF_B;               // 81920

    cudaFuncSetAttribute(gnn8_mma_gemm,
                         cudaFuncAttributeMaxDynamicSharedMemorySize, GEMM_SMEM);

    // ---- dtype detect + CSR build ----
    gnn8_detect_kernel<<<1, 1024>>>((const int*)ei);
    gnn8_init_kernel<<<nodeBlocks, T>>>();
    gnn8_count_kernel<<<edgeBlocks, T>>>(ei, E);
    gnn8_scanA_kernel<<<SCAN_NB, 1024>>>();
    gnn8_scanB_kernel<<<1, 32>>>();
    gnn8_scanC_kernel<<<SCAN_NB, 1024>>>();
    gnn8_dinv_kernel<<<nodeBlocks, T>>>();
    gnn8_fill_kernel<<<edgeBlocks, T>>>(ei, E);

    // ---- operand prep ----
    gnn8_xsplit_kernel<<<(N_NODES * (IN_DIM / 4) + T - 1) / T, T>>>(x);
    gnn8_wsplit_kernel<<<(HIDDEN * IN_DIM + T - 1) / T, T>>>(W1, IN_DIM, HIDDEN, HIDDEN, 0);
    gnn8_wsplit_kernel<<<(HIDDEN * HIDDEN + T - 1) / T, T>>>(W2, HIDDEN, HIDDEN, HIDDEN, 1);
    gnn8_wsplit_kernel<<<(NPAD_FC * HIDDEN + T - 1) / T, T>>>(Wfc, HIDDEN, N_CLASSES, NPAD_FC, 2);

    // ---- layer 1 ----
    {
        dim3 grid(mBlocks, HIDDEN / 128);
        gnn8_mma_gemm<<<grid, 256, GEMM_SMEM>>>(0, 0, nullptr, 0, nullptr, 0,
                                                IN_DIM, HIDDEN, N_NODES, HIDDEN, IN_DIM);
    }
    gnn8_gather_kernel<<<gatherBlocks, T>>>(b1);

    // ---- layer 2 ----
    {
        dim3 grid(mBlocks, HIDDEN / 128);
        gnn8_mma_gemm<<<grid, 256, GEMM_SMEM>>>(1, 1, nullptr, 0, nullptr, 0,
                                                HIDDEN, HIDDEN, N_NODES, HIDDEN, HIDDEN);
    }
    gnn8_gather_kernel<<<gatherBlocks, T>>>(b2);

    // ---- fc head ----
    {
        dim3 grid(mBlocks, NPAD_FC / 128);
        gnn8_mma_gemm<<<grid, 256, GEMM_SMEM>>>(1, 2, bfc, 1, out, 1,
                                                HIDDEN, N_CLASSES, N_NODES, N_CLASSES, HIDDEN);
    }
}

// round 14
// speedup vs baseline: 2.3236x; 1.0644x over previous
#include <cuda_runtime.h>
#include <cuda_bf16.h>
#include <cstdint>

#define N_NODES   100000
#define MAX_EDGES 3400000
#define IN_DIM    512
#define HIDDEN    256
#define N_CLASSES 1000
#define NPAD_FC   1024
#define SCAN_NB   98

// ---------------------------------------------------------------------------
// Scratch: __device__ globals. RULE: never passed as host-side kernel args —
// resolved inside kernels via selector ints (GB300 ATS makes the
// host-shadow-symbol bug silent instead of a crash; round-11 lesson).
// ---------------------------------------------------------------------------
__device__ int   g_is64;
__device__ int   g_cnt[N_NODES];
__device__ int   g_cursor[N_NODES];
__device__ int   g_rowptr[N_NODES + 1];
__device__ float g_dinv[N_NODES];
__device__ float g_scale[N_NODES];
__device__ int   g_csr_src[MAX_EDGES];
__device__ float g_csr_nrm[MAX_EDGES];
__device__ int   g_bsum[SCAN_NB];
__device__ int   g_boff[SCAN_NB];
__device__ __align__(16) float          g_h[(size_t)N_NODES * HIDDEN];
__device__ __align__(16) unsigned short g_hq[(size_t)N_NODES * HIDDEN];
__device__ __align__(16) __nv_bfloat16 g_xhi[(size_t)N_NODES * IN_DIM];
__device__ __align__(16) __nv_bfloat16 g_xlo[(size_t)N_NODES * IN_DIM];
__device__ __align__(16) __nv_bfloat16 g_ahi[(size_t)N_NODES * HIDDEN];
__device__ __align__(16) __nv_bfloat16 g_alo[(size_t)N_NODES * HIDDEN];
__device__ __align__(16) __nv_bfloat16 g_w1hi[HIDDEN * IN_DIM];
__device__ __align__(16) __nv_bfloat16 g_w1lo[HIDDEN * IN_DIM];
__device__ __align__(16) __nv_bfloat16 g_w2hi[HIDDEN * HIDDEN];
__device__ __align__(16) __nv_bfloat16 g_w2lo[HIDDEN * HIDDEN];
__device__ __align__(16) __nv_bfloat16 g_wfhi[NPAD_FC * HIDDEN];
__device__ __align__(16) __nv_bfloat16 g_wflo[NPAD_FC * HIDDEN];

// ---------------------------------------------------------------------------
// helpers
// ---------------------------------------------------------------------------
__device__ __forceinline__ uint32_t smem_u32(const void* p) {
    uint32_t a;
    asm("{ .reg .u64 t; cvta.to.shared.u64 t, %1; cvt.u32.u64 %0, t; }"
        : "=r"(a) : "l"(p));
    return a;
}
__device__ __forceinline__ void split1(float v, __nv_bfloat16& h, __nv_bfloat16& l) {
    h = __float2bfloat16_rn(v);
    l = __float2bfloat16_rn(v - __bfloat162float(h));
}
__device__ __forceinline__ int edge_at(const void* ei, long long i) {
    if (g_is64) return (int)((const long long*)ei)[i];
    return ((const int*)ei)[i];
}
__device__ __forceinline__ int clamp_node(int v) {
    return (v < 0) ? 0 : (v >= N_NODES ? N_NODES - 1 : v);
}

#define CPA16(s, g, p) \
    asm volatile("cp.async.cg.shared.global [%0], [%1], 16, %2;" \
                 :: "r"(s), "l"(g), "r"((p) ? 16 : 0))
#define CPA_COMMIT() asm volatile("cp.async.commit_group;" ::: "memory")
#define CPA_WAIT(n)  asm volatile("cp.async.wait_group %0;" :: "n"(n) : "memory")

// ---------------------------------------------------------------------------
// init + dtype detect (fused). Block 0 also samples 2048 odd 32-bit words.
// ---------------------------------------------------------------------------
__global__ void gnn9_init_detect_kernel(const int* __restrict__ ei32) {
    int i = blockIdx.x * blockDim.x + threadIdx.x;
    if (i < N_NODES) { g_cnt[i] = 0; g_cursor[i] = 0; }
    if (blockIdx.x == 0) {
        int nz = 0;
        for (int j = threadIdx.x; j < 2048; j += blockDim.x)
            if (ei32[2 * j + 1] != 0) nz = 1;
        int total = __syncthreads_count(nz);
        if (threadIdx.x == 0) g_is64 = (total == 0) ? 1 : 0;
    }
}

// ---------------------------------------------------------------------------
// CSR build
// ---------------------------------------------------------------------------
__global__ void gnn9_count_kernel(const void* __restrict__ ei, int E) {
    int e = blockIdx.x * blockDim.x + threadIdx.x;
    if (e < E) atomicAdd(&g_cnt[clamp_node(edge_at(ei, (long long)E + e))], 1);
}

__global__ void gnn9_scanA_kernel() {
    __shared__ int wsum[32];
    int i = blockIdx.x * 1024 + threadIdx.x;
    int v = (i < N_NODES) ? g_cnt[i] : 0;
    int s = v;
    for (int o = 16; o > 0; o >>= 1) s += __shfl_down_sync(0xFFFFFFFF, s, o);
    if ((threadIdx.x & 31) == 0) wsum[threadIdx.x >> 5] = s;
    __syncthreads();
    if (threadIdx.x < 32) {
        int t = wsum[threadIdx.x];
        for (int o = 16; o > 0; o >>= 1) t += __shfl_down_sync(0xFFFFFFFF, t, o);
        if (threadIdx.x == 0) g_bsum[blockIdx.x] = t;
    }
}

__global__ void gnn9_scanB_kernel() {
    if (threadIdx.x == 0) {
        int run = 0;
        for (int i = 0; i < SCAN_NB; i++) { g_boff[i] = run; run += g_bsum[i]; }
    }
}

// scanC + dinv fused
__global__ void gnn9_scanC_kernel() {
    __shared__ int s[1024];
    int t = threadIdx.x;
    int i = blockIdx.x * 1024 + t;
    int v = (i < N_NODES) ? g_cnt[i] : 0;
    s[t] = v;
    __syncthreads();
    for (int off = 1; off < 1024; off <<= 1) {
        int add = (t >= off) ? s[t - off] : 0;
        __syncthreads();
        s[t] += add;
        __syncthreads();
    }
    int excl = s[t] - v + g_boff[blockIdx.x];
    if (i < N_NODES) {
        g_rowptr[i] = excl;
        g_dinv[i] = rsqrtf((float)v + 1.0f);   // +1 self loop
        if (i == N_NODES - 1) g_rowptr[N_NODES] = excl + v;
    }
}

__global__ void gnn9_fill_kernel(const void* __restrict__ ei, int E) {
    int e = blockIdx.x * blockDim.x + threadIdx.x;
    if (e >= E) return;
    int r = clamp_node(edge_at(ei, e));
    int c = clamp_node(edge_at(ei, (long long)E + e));
    int pos = atomicAdd(&g_cursor[c], 1);
    int idx = g_rowptr[c] + pos;
    if (idx >= 0 && idx < MAX_EDGES) {
        g_csr_src[idx] = r;
        g_csr_nrm[idx] = g_dinv[r] * g_dinv[c];
    }
}

// ---------------------------------------------------------------------------
// fused split kernel: x (float4 granularity) + W1 + W2 + Wfc (elem granularity)
// ---------------------------------------------------------------------------
#define XB4   (N_NODES * (IN_DIM / 4))      // 12,800,000 float4s
#define XBLK  (XB4 / 256)                   // 50,000 blocks (exact)
#define W1E   (HIDDEN * IN_DIM)             // 131072
#define W2E   (HIDDEN * HIDDEN)             // 65536
#define WFE   (NPAD_FC * HIDDEN)            // 262144
#define W1BLK (W1E / 256)                   // 512
#define W2BLK (W2E / 256)                   // 256
#define WFBLK (WFE / 256)                   // 1024

__device__ __forceinline__ void wsplit_body(const float* __restrict__ W,
                                            int K, int N, int idx,
                                            __nv_bfloat16* hi, __nv_bfloat16* lo) {
    int n = idx / K, k = idx % K;
    float v = (n < N) ? W[(size_t)k * N + n] : 0.0f;
    __nv_bfloat16 h, l;
    split1(v, h, l);
    hi[idx] = h;
    lo[idx] = l;
}

__global__ void gnn9_split_all(const float* __restrict__ x,
                               const float* __restrict__ W1,
                               const float* __restrict__ W2,
                               const float* __restrict__ Wfc) {
    int b = blockIdx.x;
    int t = threadIdx.x;
    if (b < XBLK) {
        int idx = b * 256 + t;
        float4 v = ((const float4*)x)[idx];
        __nv_bfloat16 h0, h1, h2, h3, l0, l1, l2, l3;
        split1(v.x, h0, l0); split1(v.y, h1, l1);
        split1(v.z, h2, l2); split1(v.w, h3, l3);
        __nv_bfloat162 ph0; ph0.x = h0; ph0.y = h1;
        __nv_bfloat162 ph1; ph1.x = h2; ph1.y = h3;
        __nv_bfloat162 pl0; pl0.x = l0; pl0.y = l1;
        __nv_bfloat162 pl1; pl1.x = l2; pl1.y = l3;
        ((__nv_bfloat162*)g_xhi)[idx * 2]     = ph0;
        ((__nv_bfloat162*)g_xhi)[idx * 2 + 1] = ph1;
        ((__nv_bfloat162*)g_xlo)[idx * 2]     = pl0;
        ((__nv_bfloat162*)g_xlo)[idx * 2 + 1] = pl1;
    } else if (b < XBLK + W1BLK) {
        wsplit_body(W1, IN_DIM, HIDDEN, (b - XBLK) * 256 + t, g_w1hi, g_w1lo);
    } else if (b < XBLK + W1BLK + W2BLK) {
        wsplit_body(W2, HIDDEN, HIDDEN, (b - XBLK - W1BLK) * 256 + t, g_w2hi, g_w2lo);
    } else {
        wsplit_body(Wfc, HIDDEN, N_CLASSES, (b - XBLK - W1BLK - W2BLK) * 256 + t,
                    g_wfhi, g_wflo);
    }
}

// ---------------------------------------------------------------------------
// row quantization: warp per node. g_hq = biased-u16 rint(h/scale)+32768,
// g_scale = rowmax/32704. lane handles dims [8*lane, 8*lane+8).
// ---------------------------------------------------------------------------
__global__ __launch_bounds__(256)
void gnn9_quant_kernel() {
    int warp = (blockIdx.x * blockDim.x + threadIdx.x) >> 5;
    int lane = threadIdx.x & 31;
    if (warp >= N_NODES) return;

    const float4* hn = (const float4*)(g_h + (size_t)warp * HIDDEN);
    float4 v0 = hn[2 * lane];
    float4 v1 = hn[2 * lane + 1];
    float vals[8] = {v0.x, v0.y, v0.z, v0.w, v1.x, v1.y, v1.z, v1.w};

    float m = 0.0f;
#pragma unroll
    for (int j = 0; j < 8; j++) m = fmaxf(m, fabsf(vals[j]));
    for (int o = 16; o > 0; o >>= 1) m = fmaxf(m, __shfl_xor_sync(0xFFFFFFFF, m, o));

    float scale = (m > 0.0f) ? (m / 32704.0f) : 1.0f;
    float inv   = (m > 0.0f) ? (32704.0f / m) : 0.0f;
    if (lane == 0) g_scale[warp] = scale;

    uint32_t p[4];
#pragma unroll
    for (int q = 0; q < 4; q++) {
        uint32_t u0 = (uint32_t)(__float2int_rn(vals[2 * q]     * inv) + 32768);
        uint32_t u1 = (uint32_t)(__float2int_rn(vals[2 * q + 1] * inv) + 32768);
        p[q] = (u0 & 0xFFFFu) | (u1 << 16);
    }
    uint4 w; w.x = p[0]; w.y = p[1]; w.z = p[2]; w.w = p[3];
    ((uint4*)g_hq)[(size_t)warp * 32 + lane] = w;
}

// ---------------------------------------------------------------------------
// gather: warp per node, int16 dequant via PRMT magic-float (exact subtract).
// acc = sum_e q*(scale_src*nrm) + h[node]*dinv^2; then +bias, relu, bf16 split.
// lane handles dims [8*lane, 8*lane+8).
// ---------------------------------------------------------------------------
__global__ __launch_bounds__(256)
void gnn9_gather_kernel(const float* __restrict__ bias) {
    int warp = (blockIdx.x * blockDim.x + threadIdx.x) >> 5;
    int lane = threadIdx.x & 31;
    if (warp >= N_NODES) return;
    const int node = warp;

    float s  = g_dinv[node];
    float s2 = s * s;

    // self term (exact fp32)
    const float4* hn = (const float4*)(g_h + (size_t)node * HIDDEN);
    float4 v0 = hn[2 * lane];
    float4 v1 = hn[2 * lane + 1];
    float acc[8] = {v0.x * s2, v0.y * s2, v0.z * s2, v0.w * s2,
                    v1.x * s2, v1.y * s2, v1.z * s2, v1.w * s2};

    int beg = g_rowptr[node];
    int end = g_rowptr[node + 1];
    const uint4* hq = (const uint4*)g_hq;
#pragma unroll 4
    for (int e = beg; e < end; e++) {
        int   src = g_csr_src[e];
        float f   = g_csr_nrm[e] * g_scale[src];
        uint4 w = hq[(size_t)src * 32 + lane];
        uint32_t ws[4] = {w.x, w.y, w.z, w.w};
#pragma unroll
        for (int q = 0; q < 4; q++) {
            float t0 = __uint_as_float(__byte_perm(ws[q], 0x4B004B00u, 0x5410)) - 8421376.0f;
            float t1 = __uint_as_float(__byte_perm(ws[q], 0x4B004B00u, 0x5432)) - 8421376.0f;
            acc[2 * q]     = fmaf(t0, f, acc[2 * q]);
            acc[2 * q + 1] = fmaf(t1, f, acc[2 * q + 1]);
        }
    }

    float4 b0 = ((const float4*)bias)[2 * lane];
    float4 b1 = ((const float4*)bias)[2 * lane + 1];
    float bb[8] = {b0.x, b0.y, b0.z, b0.w, b1.x, b1.y, b1.z, b1.w};

    uint32_t ph[4], pl[4];
#pragma unroll
    for (int q = 0; q < 4; q++) {
        float va = fmaxf(acc[2 * q]     + bb[2 * q],     0.0f);
        float vb = fmaxf(acc[2 * q + 1] + bb[2 * q + 1], 0.0f);
        __nv_bfloat16 ha, la, hb, lb;
        split1(va, ha, la);
        split1(vb, hb, lb);
        __nv_bfloat162 hp; hp.x = ha; hp.y = hb;
        __nv_bfloat162 lp; lp.x = la; lp.y = lb;
        ph[q] = *(uint32_t*)&hp;
        pl[q] = *(uint32_t*)&lp;
    }
    uint4 wh; wh.x = ph[0]; wh.y = ph[1]; wh.z = ph[2]; wh.w = ph[3];
    uint4 wl; wl.x = pl[0]; wl.y = pl[1]; wl.z = pl[2]; wl.w = pl[3];
    *(uint4*)(g_ahi + (size_t)node * HIDDEN + 8 * lane) = wh;
    *(uint4*)(g_alo + (size_t)node * HIDDEN + 8 * lane) = wl;
}

// ---------------------------------------------------------------------------
// mma.sync split-bf16 GEMM, cp.async double-buffered (round-13 proven).
// a_sel: 0 -> g_xhi/g_xlo, 1 -> g_ahi/g_alo.  b_sel: 0/1/2 -> W1/W2/Wfc.
// c_sel: 0 -> g_h, 1 -> Cext.
// ---------------------------------------------------------------------------
#define SMS 40
#define TILE_B (128 * SMS * 2)
#define BUF_B  (4 * TILE_B)

__device__ __forceinline__ void ldmx4(uint32_t* r, uint32_t addr) {
    asm volatile("ldmatrix.sync.aligned.m8n8.x4.shared.b16 {%0,%1,%2,%3}, [%4];"
                 : "=r"(r[0]), "=r"(r[1]), "=r"(r[2]), "=r"(r[3]) : "r"(addr));
}
__device__ __forceinline__ void mma16816(float* d, const uint32_t* a,
                                         uint32_t b0, uint32_t b1) {
    asm volatile(
        "mma.sync.aligned.m16n8k16.row.col.f32.bf16.bf16.f32 "
        "{%0,%1,%2,%3}, {%4,%5,%6,%7}, {%8,%9}, {%0,%1,%2,%3};"
        : "+f"(d[0]), "+f"(d[1]), "+f"(d[2]), "+f"(d[3])
        : "r"(a[0]), "r"(a[1]), "r"(a[2]), "r"(a[3]), "r"(b0), "r"(b1));
}

__global__ __launch_bounds__(256, 2)
void gnn9_mma_gemm(int a_sel, int b_sel,
                   const float* __restrict__ bias, int has_bias,
                   float* __restrict__ Cext, int c_sel,
                   int lda, int ldc, int M, int Nvalid, int K) {
    const __nv_bfloat16* Ahi = a_sel ? g_ahi : g_xhi;
    const __nv_bfloat16* Alo = a_sel ? g_alo : g_xlo;
    const __nv_bfloat16* Bhi = (b_sel == 0) ? g_w1hi : (b_sel == 1) ? g_w2hi : g_wfhi;
    const __nv_bfloat16* Blo = (b_sel == 0) ? g_w1lo : (b_sel == 1) ? g_w2lo : g_wflo;
    float* C = c_sel ? Cext : (float*)g_h;

    extern __shared__ char dsm[];

    const int tid  = threadIdx.x;
    const int lane = tid & 31;
    const int wid  = tid >> 5;
    const int wm   = wid & 3;
    const int wn   = wid >> 2;
    const int m0   = blockIdx.x * 128;
    const int n0   = blockIdx.y * 128;

    float acc[2][8][4];
#pragma unroll
    for (int i = 0; i < 2; i++)
#pragma unroll
        for (int j = 0; j < 8; j++)
#pragma unroll
            for (int q = 0; q < 4; q++) acc[i][j][q] = 0.0f;

    const int a_r = (lane & 15);
    const int a_c = ((lane >> 4) << 3);
    const int b_r = (lane & 7) + ((lane >> 4) << 3);
    const int b_c = (((lane >> 3) & 1) << 3);

    auto stage = [&](int buf, int kb) {
        char* base = dsm + buf * BUF_B;
        __nv_bfloat16* sAh = (__nv_bfloat16*)(base);
        __nv_bfloat16* sAl = (__nv_bfloat16*)(base + TILE_B);
        __nv_bfloat16* sBh = (__nv_bfloat16*)(base + 2 * TILE_B);
        __nv_bfloat16* sBl = (__nv_bfloat16*)(base + 3 * TILE_B);
#pragma unroll
        for (int j = tid; j < 512; j += 256) {
            int r = j >> 2, q = j & 3;
            int gm = m0 + r;
            bool p = gm < M;
            int gmc = p ? gm : (M - 1);
            const __nv_bfloat16* ph = Ahi + (size_t)gmc * lda + kb + q * 8;
            const __nv_bfloat16* pl = Alo + (size_t)gmc * lda + kb + q * 8;
            CPA16(smem_u32(&sAh[r * SMS + q * 8]), ph, p);
            CPA16(smem_u32(&sAl[r * SMS + q * 8]), pl, p);
        }
#pragma unroll
        for (int j = tid; j < 512; j += 256) {
            int r = j >> 2, q = j & 3;
            const __nv_bfloat16* ph = Bhi + (size_t)(n0 + r) * lda + kb + q * 8;
            const __nv_bfloat16* pl = Blo + (size_t)(n0 + r) * lda + kb + q * 8;
            CPA16(smem_u32(&sBh[r * SMS + q * 8]), ph, true);
            CPA16(smem_u32(&sBl[r * SMS + q * 8]), pl, true);
        }
        CPA_COMMIT();
    };

    const int nk = K >> 5;
    stage(0, 0);

    for (int kc = 0; kc < nk; kc++) {
        const int buf = kc & 1;
        if (kc + 1 < nk) {
            stage(buf ^ 1, (kc + 1) << 5);
            CPA_WAIT(1);
        } else {
            CPA_WAIT(0);
        }
        __syncthreads();

        char* base = dsm + buf * BUF_B;
        __nv_bfloat16* sAh = (__nv_bfloat16*)(base);
        __nv_bfloat16* sAl = (__nv_bfloat16*)(base + TILE_B);
        __nv_bfloat16* sBh = (__nv_bfloat16*)(base + 2 * TILE_B);
        __nv_bfloat16* sBl = (__nv_bfloat16*)(base + 3 * TILE_B);

#pragma unroll
        for (int ks = 0; ks < 32; ks += 16) {
#pragma unroll
            for (int pass = 0; pass < 3; pass++) {
                const __nv_bfloat16* tA = (pass == 1) ? sAl : sAh;
                const __nv_bfloat16* tB = (pass == 2) ? sBl : sBh;

                uint32_t a[2][4];
#pragma unroll
                for (int im = 0; im < 2; im++) {
                    int row = wm * 32 + im * 16 + a_r;
                    ldmx4(a[im], smem_u32(&tA[row * SMS + ks + a_c]));
                }
                uint32_t b[8][2];
#pragma unroll
                for (int p = 0; p < 4; p++) {
                    uint32_t r4[4];
                    int row = wn * 64 + p * 16 + b_r;
                    ldmx4(r4, smem_u32(&tB[row * SMS + ks + b_c]));
                    b[2 * p][0]     = r4[0];
                    b[2 * p][1]     = r4[1];
                    b[2 * p + 1][0] = r4[2];
                    b[2 * p + 1][1] = r4[3];
                }
#pragma unroll
                for (int im = 0; im < 2; im++)
#pragma unroll
                    for (int in = 0; in < 8; in++)
                        mma16816(acc[im][in], a[im], b[in][0], b[in][1]);
            }
        }
        __syncthreads();
    }

#pragma unroll
    for (int im = 0; im < 2; im++) {
        int r0 = m0 + wm * 32 + im * 16 + (lane >> 2);
        int r1 = r0 + 8;
#pragma unroll
        for (int in = 0; in < 8; in++) {
            int gn = n0 + wn * 64 + in * 8 + (lane & 3) * 2;
            if (gn >= Nvalid) continue;
            float bx = 0.f, by = 0.f;
            if (has_bias) {
                float2 bb = *(const float2*)(bias + gn);
                bx = bb.x; by = bb.y;
            }
            if (r0 < M) {
                float2 v; v.x = acc[im][in][0] + bx; v.y = acc[im][in][1] + by;
                *(float2*)(C + (size_t)r0 * ldc + gn) = v;
            }
            if (r1 < M) {
                float2 v; v.x = acc[im][in][2] + bx; v.y = acc[im][in][3] + by;
                *(float2*)(C + (size_t)r1 * ldc + gn) = v;
            }
        }
    }
}

// ---------------------------------------------------------------------------
// launch
// ---------------------------------------------------------------------------
extern "C" void kernel_launch(void* const* d_in, const int* in_sizes, int n_in,
                              void* d_out, int out_size) {
    const float* x   = (const float*)d_in[0];
    const void*  ei  = d_in[1];
    const float* W1  = (const float*)d_in[2];
    const float* b1  = (const float*)d_in[3];
    const float* W2  = (const float*)d_in[4];
    const float* b2  = (const float*)d_in[5];
    const float* Wfc = (const float*)d_in[6];
    const float* bfc = (const float*)d_in[7];
    float*       out = (float*)d_out;

    const int E = in_sizes[1] / 2;

    const int T = 256;
    const int nodeBlocks   = (N_NODES + T - 1) / T;
    const int edgeBlocks   = (E + T - 1) / T;
    const int warpNodeBlks = (N_NODES + 7) / 8;     // warp-per-node kernels
    const int mBlocks      = (N_NODES + 127) / 128; // 782
    const int GEMM_SMEM    = 2 * BUF_B;             // 81920
    const int splitBlocks  = XBLK + W1BLK + W2BLK + WFBLK;

    cudaFuncSetAttribute(gnn9_mma_gemm,
                         cudaFuncAttributeMaxDynamicSharedMemorySize, GEMM_SMEM);

    // ---- dtype detect + CSR build ----
    gnn9_init_detect_kernel<<<nodeBlocks, T>>>((const int*)ei);
    gnn9_count_kernel<<<edgeBlocks, T>>>(ei, E);
    gnn9_scanA_kernel<<<SCAN_NB, 1024>>>();
    gnn9_scanB_kernel<<<1, 32>>>();
    gnn9_scanC_kernel<<<SCAN_NB, 1024>>>();
    gnn9_fill_kernel<<<edgeBlocks, T>>>(ei, E);

    // ---- operand prep (fused splits) ----
    gnn9_split_all<<<splitBlocks, T>>>(x, W1, W2, Wfc);

    // ---- layer 1 ----
    {
        dim3 grid(mBlocks, HIDDEN / 128);
        gnn9_mma_gemm<<<grid, 256, GEMM_SMEM>>>(0, 0, nullptr, 0, nullptr, 0,
                                                IN_DIM, HIDDEN, N_NODES, HIDDEN, IN_DIM);
    }
    gnn9_quant_kernel<<<warpNodeBlks, T>>>();
    gnn9_gather_kernel<<<warpNodeBlks, T>>>(b1);

    // ---- layer 2 ----
    {
        dim3 grid(mBlocks, HIDDEN / 128);
        gnn9_mma_gemm<<<grid, 256, GEMM_SMEM>>>(1, 1, nullptr, 0, nullptr, 0,
                                                HIDDEN, HIDDEN, N_NODES, HIDDEN, HIDDEN);
    }
    gnn9_quant_kernel<<<warpNodeBlks, T>>>();
    gnn9_gather_kernel<<<warpNodeBlks, T>>>(b2);

    // ---- fc head ----
    {
        dim3 grid(mBlocks, NPAD_FC / 128);
        gnn9_mma_gemm<<<grid, 256, GEMM_SMEM>>>(1, 2, bfc, 1, out, 1,
                                                HIDDEN, N_CLASSES, N_NODES, N_CLASSES, HIDDEN);
    }
}

// round 17
// speedup vs baseline: 2.3613x; 1.0162x over previous
#include <cuda_runtime.h>
#include <cuda_bf16.h>
#include <cstdint>

#define N_NODES   100000
#define MAX_EDGES 3400000
#define IN_DIM    512
#define HIDDEN    256
#define N_CLASSES 1000
#define NPAD_FC   1024
#define SCAN_NB   98

// ---------------------------------------------------------------------------
// Scratch: __device__ globals. RULE: never passed as host-side kernel args —
// resolved inside kernels via selector ints (round-11 lesson). Every array
// accessed through a vector cast carries explicit __align__(16).
// ---------------------------------------------------------------------------
__device__ int   g_is64;
__device__ int   g_cnt[N_NODES];
__device__ int   g_cursor[N_NODES];
__device__ int   g_rowptr[N_NODES + 1];
__device__ float g_dinv[N_NODES];
__device__ __align__(16) float g_scale2[2 * N_NODES];   // read as float2!
__device__ int   g_csr_src[MAX_EDGES];
__device__ float g_csr_nrm[MAX_EDGES];
__device__ int   g_bsum[SCAN_NB];
__device__ int   g_boff[SCAN_NB];
__device__ __align__(16) unsigned short g_hq[(size_t)N_NODES * HIDDEN];
__device__ __align__(16) __nv_bfloat16 g_xhi[(size_t)N_NODES * IN_DIM];
__device__ __align__(16) __nv_bfloat16 g_xlo[(size_t)N_NODES * IN_DIM];
__device__ __align__(16) __nv_bfloat16 g_ahi[(size_t)N_NODES * HIDDEN];
__device__ __align__(16) __nv_bfloat16 g_alo[(size_t)N_NODES * HIDDEN];
__device__ __align__(16) __nv_bfloat16 g_w1hi[HIDDEN * IN_DIM];
__device__ __align__(16) __nv_bfloat16 g_w1lo[HIDDEN * IN_DIM];
__device__ __align__(16) __nv_bfloat16 g_w2hi[HIDDEN * HIDDEN];
__device__ __align__(16) __nv_bfloat16 g_w2lo[HIDDEN * HIDDEN];
__device__ __align__(16) __nv_bfloat16 g_wfhi[NPAD_FC * HIDDEN];
__device__ __align__(16) __nv_bfloat16 g_wflo[NPAD_FC * HIDDEN];

// ---------------------------------------------------------------------------
// helpers
// ---------------------------------------------------------------------------
__device__ __forceinline__ uint32_t smem_u32(const void* p) {
    uint32_t a;
    asm("{ .reg .u64 t; cvta.to.shared.u64 t, %1; cvt.u32.u64 %0, t; }"
        : "=r"(a) : "l"(p));
    return a;
}
__device__ __forceinline__ void split1(float v, __nv_bfloat16& h, __nv_bfloat16& l) {
    h = __float2bfloat16_rn(v);
    l = __float2bfloat16_rn(v - __bfloat162float(h));
}
__device__ __forceinline__ int edge_at(const void* ei, long long i) {
    if (g_is64) return (int)((const long long*)ei)[i];
    return ((const int*)ei)[i];
}
__device__ __forceinline__ int clamp_node(int v) {
    return (v < 0) ? 0 : (v >= N_NODES ? N_NODES - 1 : v);
}

#define CPA16(s, g, p) \
    asm volatile("cp.async.cg.shared.global [%0], [%1], 16, %2;" \
                 :: "r"(s), "l"(g), "r"((p) ? 16 : 0))
#define CPA_COMMIT() asm volatile("cp.async.commit_group;" ::: "memory")
#define CPA_WAIT(n)  asm volatile("cp.async.wait_group %0;" :: "n"(n) : "memory")

// ---------------------------------------------------------------------------
// init + dtype detect (fused)
// ---------------------------------------------------------------------------
__global__ void gnnB_init_detect_kernel(const int* __restrict__ ei32) {
    int i = blockIdx.x * blockDim.x + threadIdx.x;
    if (i < N_NODES) { g_cnt[i] = 0; g_cursor[i] = 0; }
    if (blockIdx.x == 0) {
        int nz = 0;
        for (int j = threadIdx.x; j < 2048; j += blockDim.x)
            if (ei32[2 * j + 1] != 0) nz = 1;
        int total = __syncthreads_count(nz);
        if (threadIdx.x == 0) g_is64 = (total == 0) ? 1 : 0;
    }
}

// ---------------------------------------------------------------------------
// CSR build
// ---------------------------------------------------------------------------
__global__ void gnnB_count_kernel(const void* __restrict__ ei, int E) {
    int e = blockIdx.x * blockDim.x + threadIdx.x;
    if (e < E) atomicAdd(&g_cnt[clamp_node(edge_at(ei, (long long)E + e))], 1);
}

__global__ void gnnB_scanA_kernel() {
    __shared__ int wsum[32];
    int i = blockIdx.x * 1024 + threadIdx.x;
    int v = (i < N_NODES) ? g_cnt[i] : 0;
    int s = v;
    for (int o = 16; o > 0; o >>= 1) s += __shfl_down_sync(0xFFFFFFFF, s, o);
    if ((threadIdx.x & 31) == 0) wsum[threadIdx.x >> 5] = s;
    __syncthreads();
    if (threadIdx.x < 32) {
        int t = wsum[threadIdx.x];
        for (int o = 16; o > 0; o >>= 1) t += __shfl_down_sync(0xFFFFFFFF, t, o);
        if (threadIdx.x == 0) g_bsum[blockIdx.x] = t;
    }
}

__global__ void gnnB_scanB_kernel() {
    if (threadIdx.x == 0) {
        int run = 0;
        for (int i = 0; i < SCAN_NB; i++) { g_boff[i] = run; run += g_bsum[i]; }
    }
}

__global__ void gnnB_scanC_kernel() {
    __shared__ int s[1024];
    int t = threadIdx.x;
    int i = blockIdx.x * 1024 + t;
    int v = (i < N_NODES) ? g_cnt[i] : 0;
    s[t] = v;
    __syncthreads();
    for (int off = 1; off < 1024; off <<= 1) {
        int add = (t >= off) ? s[t - off] : 0;
        __syncthreads();
        s[t] += add;
        __syncthreads();
    }
    int excl = s[t] - v + g_boff[blockIdx.x];
    if (i < N_NODES) {
        g_rowptr[i] = excl;
        g_dinv[i] = rsqrtf((float)v + 1.0f);   // +1 self loop
        if (i == N_NODES - 1) g_rowptr[N_NODES] = excl + v;
    }
}

__global__ void gnnB_fill_kernel(const void* __restrict__ ei, int E) {
    int e = blockIdx.x * blockDim.x + threadIdx.x;
    if (e >= E) return;
    int r = clamp_node(edge_at(ei, e));
    int c = clamp_node(edge_at(ei, (long long)E + e));
    int pos = atomicAdd(&g_cursor[c], 1);
    int idx = g_rowptr[c] + pos;
    if (idx >= 0 && idx < MAX_EDGES) {
        g_csr_src[idx] = r;
        g_csr_nrm[idx] = g_dinv[r] * g_dinv[c];
    }
}

// ---------------------------------------------------------------------------
// fused split kernel: x (float4 granularity) + W1 + W2 + Wfc
// ---------------------------------------------------------------------------
#define XB4   (N_NODES * (IN_DIM / 4))
#define XBLK  (XB4 / 256)
#define W1E   (HIDDEN * IN_DIM)
#define W2E   (HIDDEN * HIDDEN)
#define WFE   (NPAD_FC * HIDDEN)
#define W1BLK (W1E / 256)
#define W2BLK (W2E / 256)
#define WFBLK (WFE / 256)

__device__ __forceinline__ void wsplit_body(const float* __restrict__ W,
                                            int K, int N, int idx,
                                            __nv_bfloat16* hi, __nv_bfloat16* lo) {
    int n = idx / K, k = idx % K;
    float v = (n < N) ? W[(size_t)k * N + n] : 0.0f;
    __nv_bfloat16 h, l;
    split1(v, h, l);
    hi[idx] = h;
    lo[idx] = l;
}

__global__ void gnnB_split_all(const float* __restrict__ x,
                               const float* __restrict__ W1,
                               const float* __restrict__ W2,
                               const float* __restrict__ Wfc) {
    int b = blockIdx.x;
    int t = threadIdx.x;
    if (b < XBLK) {
        int idx = b * 256 + t;
        float4 v = ((const float4*)x)[idx];
        __nv_bfloat16 h0, h1, h2, h3, l0, l1, l2, l3;
        split1(v.x, h0, l0); split1(v.y, h1, l1);
        split1(v.z, h2, l2); split1(v.w, h3, l3);
        __nv_bfloat162 ph0; ph0.x = h0; ph0.y = h1;
        __nv_bfloat162 ph1; ph1.x = h2; ph1.y = h3;
        __nv_bfloat162 pl0; pl0.x = l0; pl0.y = l1;
        __nv_bfloat162 pl1; pl1.x = l2; pl1.y = l3;
        ((__nv_bfloat162*)g_xhi)[idx * 2]     = ph0;
        ((__nv_bfloat162*)g_xhi)[idx * 2 + 1] = ph1;
        ((__nv_bfloat162*)g_xlo)[idx * 2]     = pl0;
        ((__nv_bfloat162*)g_xlo)[idx * 2 + 1] = pl1;
    } else if (b < XBLK + W1BLK) {
        wsplit_body(W1, IN_DIM, HIDDEN, (b - XBLK) * 256 + t, g_w1hi, g_w1lo);
    } else if (b < XBLK + W1BLK + W2BLK) {
        wsplit_body(W2, HIDDEN, HIDDEN, (b - XBLK - W1BLK) * 256 + t, g_w2hi, g_w2lo);
    } else {
        wsplit_body(Wfc, HIDDEN, N_CLASSES, (b - XBLK - W1BLK - W2BLK) * 256 + t,
                    g_wfhi, g_wflo);
    }
}

// ---------------------------------------------------------------------------
// gather: warp per node, int16 dequant (PRMT magic-float). Self term also
// dequantized from g_hq. Emits bf16 hi/lo splits only.
// lane handles dims [8*lane, 8*lane+8); lanes<16 = half 0, lanes>=16 = half 1.
// ---------------------------------------------------------------------------
__global__ __launch_bounds__(256)
void gnnB_gather_kernel(const float* __restrict__ bias) {
    int warp = (blockIdx.x * blockDim.x + threadIdx.x) >> 5;
    int lane = threadIdx.x & 31;
    if (warp >= N_NODES) return;
    const int node = warp;
    const int half = lane >> 4;

    float s  = g_dinv[node];
    float s2 = s * s;

    const uint4* hq = (const uint4*)g_hq;

    // self term (dequantized)
    float acc[8];
    {
        float2 sc = ((const float2*)g_scale2)[node];
        float fs = (half ? sc.y : sc.x) * s2;
        uint4 w = hq[(size_t)node * 32 + lane];
        uint32_t ws[4] = {w.x, w.y, w.z, w.w};
#pragma unroll
        for (int q = 0; q < 4; q++) {
            float t0 = __uint_as_float(__byte_perm(ws[q], 0x4B004B00u, 0x5410)) - 8421376.0f;
            float t1 = __uint_as_float(__byte_perm(ws[q], 0x4B004B00u, 0x5432)) - 8421376.0f;
            acc[2 * q]     = t0 * fs;
            acc[2 * q + 1] = t1 * fs;
        }
    }

    int beg = g_rowptr[node];
    int end = g_rowptr[node + 1];
#pragma unroll 4
    for (int e = beg; e < end; e++) {
        int   src = g_csr_src[e];
        float nrm = g_csr_nrm[e];
        float2 sc = ((const float2*)g_scale2)[src];
        float f = nrm * (half ? sc.y : sc.x);
        uint4 w = hq[(size_t)src * 32 + lane];
        uint32_t ws[4] = {w.x, w.y, w.z, w.w};
#pragma unroll
        for (int q = 0; q < 4; q++) {
            float t0 = __uint_as_float(__byte_perm(ws[q], 0x4B004B00u, 0x5410)) - 8421376.0f;
            float t1 = __uint_as_float(__byte_perm(ws[q], 0x4B004B00u, 0x5432)) - 8421376.0f;
            acc[2 * q]     = fmaf(t0, f, acc[2 * q]);
            acc[2 * q + 1] = fmaf(t1, f, acc[2 * q + 1]);
        }
    }

    float4 b0 = ((const float4*)bias)[2 * lane];
    float4 b1 = ((const float4*)bias)[2 * lane + 1];
    float bb[8] = {b0.x, b0.y, b0.z, b0.w, b1.x, b1.y, b1.z, b1.w};

    uint32_t ph[4], pl[4];
#pragma unroll
    for (int q = 0; q < 4; q++) {
        float va = fmaxf(acc[2 * q]     + bb[2 * q],     0.0f);
        float vb = fmaxf(acc[2 * q + 1] + bb[2 * q + 1], 0.0f);
        __nv_bfloat16 ha, la, hb, lb;
        split1(va, ha, la);
        split1(vb, hb, lb);
        __nv_bfloat162 hp; hp.x = ha; hp.y = hb;
        __nv_bfloat162 lp; lp.x = la; lp.y = lb;
        ph[q] = *(uint32_t*)&hp;
        pl[q] = *(uint32_t*)&lp;
    }
    uint4 wh; wh.x = ph[0]; wh.y = ph[1]; wh.z = ph[2]; wh.w = ph[3];
    uint4 wl; wl.x = pl[0]; wl.y = pl[1]; wl.z = pl[2]; wl.w = pl[3];
    *(uint4*)(g_ahi + (size_t)node * HIDDEN + 8 * lane) = wh;
    *(uint4*)(g_alo + (size_t)node * HIDDEN + 8 * lane) = wl;
}

// ---------------------------------------------------------------------------
// mma.sync split-bf16 GEMM, cp.async double-buffered, fragment-reuse mainloop.
// c_sel 0: quantized epilogue -> g_hq + g_scale2 (N=256, half=blockIdx.y)
// c_sel 1: float epilogue (+bias) -> Cext
// ---------------------------------------------------------------------------
#define SMS 40
#define TILE_B (128 * SMS * 2)
#define BUF_B  (4 * TILE_B)
#define GEMM_SMEM (2 * BUF_B + 512)

__device__ __forceinline__ void ldmx4(uint32_t* r, uint32_t addr) {
    asm volatile("ldmatrix.sync.aligned.m8n8.x4.shared.b16 {%0,%1,%2,%3}, [%4];"
                 : "=r"(r[0]), "=r"(r[1]), "=r"(r[2]), "=r"(r[3]) : "r"(addr));
}
__device__ __forceinline__ void mma16816(float* d, const uint32_t* a,
                                         uint32_t b0, uint32_t b1) {
    asm volatile(
        "mma.sync.aligned.m16n8k16.row.col.f32.bf16.bf16.f32 "
        "{%0,%1,%2,%3}, {%4,%5,%6,%7}, {%8,%9}, {%0,%1,%2,%3};"
        : "+f"(d[0]), "+f"(d[1]), "+f"(d[2]), "+f"(d[3])
        : "r"(a[0]), "r"(a[1]), "r"(a[2]), "r"(a[3]), "r"(b0), "r"(b1));
}

__global__ __launch_bounds__(256, 2)
void gnnB_mma_gemm(int a_sel, int b_sel,
                   const float* __restrict__ bias, int has_bias,
                   float* __restrict__ Cext, int c_sel,
                   int lda, int ldc, int M, int Nvalid, int K) {
    const __nv_bfloat16* Ahi = a_sel ? g_ahi : g_xhi;
    const __nv_bfloat16* Alo = a_sel ? g_alo : g_xlo;
    const __nv_bfloat16* Bhi = (b_sel == 0) ? g_w1hi : (b_sel == 1) ? g_w2hi : g_wfhi;
    const __nv_bfloat16* Blo = (b_sel == 0) ? g_w1lo : (b_sel == 1) ? g_w2lo : g_wflo;

    extern __shared__ char dsm[];

    const int tid  = threadIdx.x;
    const int lane = tid & 31;
    const int wid  = tid >> 5;
    const int wm   = wid & 3;
    const int wn   = wid >> 2;
    const int m0   = blockIdx.x * 128;
    const int n0   = blockIdx.y * 128;

    float acc[2][8][4];
#pragma unroll
    for (int i = 0; i < 2; i++)
#pragma unroll
        for (int j = 0; j < 8; j++)
#pragma unroll
            for (int q = 0; q < 4; q++) acc[i][j][q] = 0.0f;

    const int a_r = (lane & 15);
    const int a_c = ((lane >> 4) << 3);
    const int b_r = (lane & 7) + ((lane >> 4) << 3);
    const int b_c = (((lane >> 3) & 1) << 3);

    auto stage = [&](int buf, int kb) {
        char* base = dsm + buf * BUF_B;
        __nv_bfloat16* sAh = (__nv_bfloat16*)(base);
        __nv_bfloat16* sAl = (__nv_bfloat16*)(base + TILE_B);
        __nv_bfloat16* sBh = (__nv_bfloat16*)(base + 2 * TILE_B);
        __nv_bfloat16* sBl = (__nv_bfloat16*)(base + 3 * TILE_B);
#pragma unroll
        for (int j = tid; j < 512; j += 256) {
            int r = j >> 2, q = j & 3;
            int gm = m0 + r;
            bool p = gm < M;
            int gmc = p ? gm : (M - 1);
            const __nv_bfloat16* ph = Ahi + (size_t)gmc * lda + kb + q * 8;
            const __nv_bfloat16* pl = Alo + (size_t)gmc * lda + kb + q * 8;
            CPA16(smem_u32(&sAh[r * SMS + q * 8]), ph, p);
            CPA16(smem_u32(&sAl[r * SMS + q * 8]), pl, p);
        }
#pragma unroll
        for (int j = tid; j < 512; j += 256) {
            int r = j >> 2, q = j & 3;
            const __nv_bfloat16* ph = Bhi + (size_t)(n0 + r) * lda + kb + q * 8;
            const __nv_bfloat16* pl = Blo + (size_t)(n0 + r) * lda + kb + q * 8;
            CPA16(smem_u32(&sBh[r * SMS + q * 8]), ph, true);
            CPA16(smem_u32(&sBl[r * SMS + q * 8]), pl, true);
        }
        CPA_COMMIT();
    };

    const int nk = K >> 5;
    stage(0, 0);

    for (int kc = 0; kc < nk; kc++) {
        const int buf = kc & 1;
        if (kc + 1 < nk) {
            stage(buf ^ 1, (kc + 1) << 5);
            CPA_WAIT(1);
        } else {
            CPA_WAIT(0);
        }
        __syncthreads();

        char* base = dsm + buf * BUF_B;
        __nv_bfloat16* sAh = (__nv_bfloat16*)(base);
        __nv_bfloat16* sAl = (__nv_bfloat16*)(base + TILE_B);
        __nv_bfloat16* sBh = (__nv_bfloat16*)(base + 2 * TILE_B);
        __nv_bfloat16* sBl = (__nv_bfloat16*)(base + 3 * TILE_B);

#pragma unroll
        for (int ks = 0; ks < 32; ks += 16) {
            // fragment-reuse: load Ahi, Bhi, Blo once; Alo overwrites Ahi.
            uint32_t a[2][4], bh[8][2], bl2[8][2];
#pragma unroll
            for (int im = 0; im < 2; im++) {
                int row = wm * 32 + im * 16 + a_r;
                ldmx4(a[im], smem_u32(&sAh[row * SMS + ks + a_c]));
            }
#pragma unroll
            for (int p = 0; p < 4; p++) {
                uint32_t r4[4];
                int row = wn * 64 + p * 16 + b_r;
                ldmx4(r4, smem_u32(&sBh[row * SMS + ks + b_c]));
                bh[2 * p][0] = r4[0]; bh[2 * p][1] = r4[1];
                bh[2 * p + 1][0] = r4[2]; bh[2 * p + 1][1] = r4[3];
            }
#pragma unroll
            for (int p = 0; p < 4; p++) {
                uint32_t r4[4];
                int row = wn * 64 + p * 16 + b_r;
                ldmx4(r4, smem_u32(&sBl[row * SMS + ks + b_c]));
                bl2[2 * p][0] = r4[0]; bl2[2 * p][1] = r4[1];
                bl2[2 * p + 1][0] = r4[2]; bl2[2 * p + 1][1] = r4[3];
            }
#pragma unroll
            for (int im = 0; im < 2; im++)
#pragma unroll
                for (int in = 0; in < 8; in++)
                    mma16816(acc[im][in], a[im], bh[in][0], bh[in][1]);
#pragma unroll
            for (int im = 0; im < 2; im++)
#pragma unroll
                for (int in = 0; in < 8; in++)
                    mma16816(acc[im][in], a[im], bl2[in][0], bl2[in][1]);
#pragma unroll
            for (int im = 0; im < 2; im++) {
                int row = wm * 32 + im * 16 + a_r;
                ldmx4(a[im], smem_u32(&sAl[row * SMS + ks + a_c]));
            }
#pragma unroll
            for (int im = 0; im < 2; im++)
#pragma unroll
                for (int in = 0; in < 8; in++)
                    mma16816(acc[im][in], a[im], bh[in][0], bh[in][1]);
        }
        __syncthreads();
    }

    if (c_sel) {
        // ---- float epilogue (+bias) ----
#pragma unroll
        for (int im = 0; im < 2; im++) {
            int r0 = m0 + wm * 32 + im * 16 + (lane >> 2);
            int r1 = r0 + 8;
#pragma unroll
            for (int in = 0; in < 8; in++) {
                int gn = n0 + wn * 64 + in * 8 + (lane & 3) * 2;
                if (gn >= Nvalid) continue;
                float bx = 0.f, by = 0.f;
                if (has_bias) {
                    float2 bb = *(const float2*)(bias + gn);
                    bx = bb.x; by = bb.y;
                }
                if (r0 < M) {
                    float2 v; v.x = acc[im][in][0] + bx; v.y = acc[im][in][1] + by;
                    *(float2*)(Cext + (size_t)r0 * ldc + gn) = v;
                }
                if (r1 < M) {
                    float2 v; v.x = acc[im][in][2] + bx; v.y = acc[im][in][3] + by;
                    *(float2*)(Cext + (size_t)r1 * ldc + gn) = v;
                }
            }
        }
    } else {
        // ---- quantized epilogue: per-row max over this CTA's 128-col half,
        //      write biased-u16 to g_hq + per-half scale to g_scale2 ----
        int* srm = (int*)(dsm + 2 * BUF_B);      // 128 ints
        if (tid < 128) srm[tid] = 0;
        __syncthreads();
#pragma unroll
        for (int im = 0; im < 2; im++) {
            int rl0 = wm * 32 + im * 16 + (lane >> 2);
            float m0v = 0.0f, m1v = 0.0f;
#pragma unroll
            for (int in = 0; in < 8; in++) {
                m0v = fmaxf(m0v, fmaxf(fabsf(acc[im][in][0]), fabsf(acc[im][in][1])));
                m1v = fmaxf(m1v, fmaxf(fabsf(acc[im][in][2]), fabsf(acc[im][in][3])));
            }
            atomicMax(&srm[rl0],     __float_as_int(m0v));
            atomicMax(&srm[rl0 + 8], __float_as_int(m1v));
        }
        __syncthreads();
        const int half = blockIdx.y;
#pragma unroll
        for (int im = 0; im < 2; im++) {
            int rl0 = wm * 32 + im * 16 + (lane >> 2);
            int r0 = m0 + rl0, r1 = r0 + 8;
            float mA = __int_as_float(srm[rl0]);
            float mB = __int_as_float(srm[rl0 + 8]);
            float invA = (mA > 0.0f) ? (32704.0f / mA) : 0.0f;
            float invB = (mB > 0.0f) ? (32704.0f / mB) : 0.0f;
#pragma unroll
            for (int in = 0; in < 8; in++) {
                int gn = n0 + wn * 64 + in * 8 + (lane & 3) * 2;
                if (r0 < M) {
                    ushort2 v;
                    v.x = (unsigned short)(__float2int_rn(acc[im][in][0] * invA) + 32768);
                    v.y = (unsigned short)(__float2int_rn(acc[im][in][1] * invA) + 32768);
                    *(ushort2*)(g_hq + (size_t)r0 * HIDDEN + gn) = v;
                }
                if (r1 < M) {
                    ushort2 v;
                    v.x = (unsigned short)(__float2int_rn(acc[im][in][2] * invB) + 32768);
                    v.y = (unsigned short)(__float2int_rn(acc[im][in][3] * invB) + 32768);
                    *(ushort2*)(g_hq + (size_t)r1 * HIDDEN + gn) = v;
                }
            }
            if (wn == 0 && (lane & 3) == 0) {
                if (r0 < M) g_scale2[2 * r0 + half] = (mA > 0.0f) ? (mA / 32704.0f) : 1.0f;
                if (r1 < M) g_scale2[2 * r1 + half] = (mB > 0.0f) ? (mB / 32704.0f) : 1.0f;
            }
        }
    }
}

// ---------------------------------------------------------------------------
// launch
// ---------------------------------------------------------------------------
extern "C" void kernel_launch(void* const* d_in, const int* in_sizes, int n_in,
                              void* d_out, int out_size) {
    const float* x   = (const float*)d_in[0];
    const void*  ei  = d_in[1];
    const float* W1  = (const float*)d_in[2];
    const float* b1  = (const float*)d_in[3];
    const float* W2  = (const float*)d_in[4];
    const float* b2  = (const float*)d_in[5];
    const float* Wfc = (const float*)d_in[6];
    const float* bfc = (const float*)d_in[7];
    float*       out = (float*)d_out;

    const int E = in_sizes[1] / 2;

    const int T = 256;
    const int nodeBlocks   = (N_NODES + T - 1) / T;
    const int edgeBlocks   = (E + T - 1) / T;
    const int warpNodeBlks = (N_NODES + 7) / 8;
    const int mBlocks      = (N_NODES + 127) / 128;   // 782
    const int splitBlocks  = XBLK + W1BLK + W2BLK + WFBLK;

    cudaFuncSetAttribute(gnnB_mma_gemm,
                         cudaFuncAttributeMaxDynamicSharedMemorySize, GEMM_SMEM);

    // ---- dtype detect + CSR build ----
    gnnB_init_detect_kernel<<<nodeBlocks, T>>>((const int*)ei);
    gnnB_count_kernel<<<edgeBlocks, T>>>(ei, E);
    gnnB_scanA_kernel<<<SCAN_NB, 1024>>>();
    gnnB_scanB_kernel<<<1, 32>>>();
    gnnB_scanC_kernel<<<SCAN_NB, 1024>>>();
    gnnB_fill_kernel<<<edgeBlocks, T>>>(ei, E);

    // ---- operand prep (fused splits) ----
    gnnB_split_all<<<splitBlocks, T>>>(x, W1, W2, Wfc);

    // ---- layer 1: hq = quant(x @ W1) ; gather -> bf16 splits ----
    {
        dim3 grid(mBlocks, HIDDEN / 128);
        gnnB_mma_gemm<<<grid, 256, GEMM_SMEM>>>(0, 0, nullptr, 0, nullptr, 0,
                                                IN_DIM, 0, N_NODES, HIDDEN, IN_DIM);
    }
    gnnB_gather_kernel<<<warpNodeBlks, T>>>(b1);

    // ---- layer 2 ----
    {
        dim3 grid(mBlocks, HIDDEN / 128);
        gnnB_mma_gemm<<<grid, 256, GEMM_SMEM>>>(1, 1, nullptr, 0, nullptr, 0,
                                                HIDDEN, 0, N_NODES, HIDDEN, HIDDEN);
    }
    gnnB_gather_kernel<<<warpNodeBlks, T>>>(b2);

    // ---- fc head: out = agg @ Wfc + bfc ----
    {
        dim3 grid(mBlocks, NPAD_FC / 128);
        gnnB_mma_gemm<<<grid, 256, GEMM_SMEM>>>(1, 2, bfc, 1, out, 1,
                                                HIDDEN, N_CLASSES, N_NODES, N_CLASSES, HIDDEN);
    }
}